// round 14
// baseline (speedup 1.0000x reference)
// v14: BN=256 everywhere + single-sync tile loop
#include <cuda_runtime.h>
#include <cuda_fp16.h>
#include <math.h>
#include <stdint.h>

// ---------------- problem constants ----------------
#define T_    4
#define V_    8
#define TVC   32
#define HP    64
#define WP    64
#define C_    64
#define KSEL  4
#define HID   256
#define TE    32
#define VE    16
#define MAXM  50000
#define MAXTOK (MAXM*KSEL)

// ---------------- scratch ----------------
__device__ float g_P[TVC*12];
__device__ float g_scal[4];
__device__ float g_temb[T_*TE];
__device__ int   g_selcam[MAXTOK];
__device__ float g_selu[MAXTOK];
__device__ float g_selv[MAXTOK];
__device__ float g_selz[MAXTOK];

// fp32 intermediates
__device__ float g_h   [(size_t)MAXTOK*256];
__device__ float g_qkv [(size_t)MAXTOK*768];

// half (h, m/8) activation buffers
__device__ __half g_xh[(size_t)MAXTOK*96],  g_xl[(size_t)MAXTOK*96];
__device__ __half g_hh[(size_t)MAXTOK*256], g_hl[(size_t)MAXTOK*256];
__device__ __half g_oh[(size_t)MAXTOK*256], g_ol[(size_t)MAXTOK*256];
__device__ __half g_fh[(size_t)MAXTOK*512], g_fl[(size_t)MAXTOK*512];
__device__ __half g_mh[(size_t)MAXM*256],   g_ml[(size_t)MAXM*256];

// preconverted transposed weights [Nout][Kd], (h, m/4)
#define WTOTAL 1089536
__device__ __half g_wh[WTOTAL], g_wl[WTOTAL];

// ---------------- setup ----------------
__global__ void setup_kernel(const float* __restrict__ poses,
                             const float* __restrict__ intr,
                             const int*   __restrict__ time_ids,
                             int T)
{
    int n = threadIdx.x;
    if (n < TVC) {
        double a[4][8];
        for (int r = 0; r < 4; r++)
            for (int c = 0; c < 4; c++) {
                a[r][c]   = (double)poses[n*16 + r*4 + c];
                a[r][4+c] = (r == c) ? 1.0 : 0.0;
            }
        for (int col = 0; col < 4; col++) {
            int piv = col;
            for (int r = col+1; r < 4; r++)
                if (fabs(a[r][col]) > fabs(a[piv][col])) piv = r;
            if (piv != col)
                for (int c = 0; c < 8; c++) { double t = a[col][c]; a[col][c] = a[piv][c]; a[piv][c] = t; }
            double dv = a[col][col];
            for (int c = 0; c < 8; c++) a[col][c] /= dv;
            for (int r = 0; r < 4; r++) if (r != col) {
                double f = a[r][col];
                for (int c = 0; c < 8; c++) a[r][c] -= f * a[col][c];
            }
        }
        double Km[9];
        for (int i = 0; i < 9; i++) Km[i] = (double)intr[n*9 + i];
        for (int r = 0; r < 3; r++)
            for (int c = 0; c < 4; c++) {
                double s = 0.0;
                for (int j = 0; j < 3; j++) s += Km[r*3 + j] * a[j][4 + c];
                g_P[n*12 + r*4 + c] = (float)s;
            }
    }
    if (n == 0) {
        float cx = intr[2], cy = intr[5];
        float W = 2.0f*cx, H = 2.0f*cy;
        g_scal[0] = W; g_scal[1] = H;
        g_scal[2] = (float)WP / fmaxf(1.0f, W);
        g_scal[3] = (float)HP / fmaxf(1.0f, H);
        int tmin = time_ids[0], tmax = time_ids[0];
        for (int t = 1; t < T; t++) {
            int v = time_ids[t];
            if (v < tmin) tmin = v;
            if (v > tmax) tmax = v;
        }
        if (tmax < tmin + 1) tmax = tmin + 1;
        for (int t = 0; t < T; t++) {
            double tn = (double)(time_ids[t] - tmin) / (double)(tmax - tmin);
            for (int i = 0; i < TE/2; i++) {
                double f  = exp(8.0 * (double)i / (double)(TE/2 - 1));
                double ph = tn * f;
                g_temb[t*TE + i]        = (float)sin(ph);
                g_temb[t*TE + TE/2 + i] = (float)cos(ph);
            }
        }
    }
}

// ---------------- single-launch weight convert + transpose ----------------
struct WTab {
    const float* src[10];
    long long    off[10];
    int          kd[10];
    int          nout[10];
};
__global__ __launch_bounds__(256)
void wconv_all(WTab tab, __half* __restrict__ Wh, __half* __restrict__ Wl)
{
    int mi  = blockIdx.y;
    int idx = blockIdx.x * blockDim.x + threadIdx.x;
    int Kd = tab.kd[mi], Nout = tab.nout[mi];
    if (idx >= Kd * Nout) return;
    int n = idx / Kd, k = idx - n*Kd;
    float w = tab.src[mi][(size_t)k*Nout + n];
    __half h = __float2half_rn(w);
    float hf = __half2float(h);
    float l  = w - hf;
    size_t o = (size_t)tab.off[mi] + idx;
    Wh[o] = h;
    Wl[o] = __float2half_rn(hf*0.25f + 8.0f*l);
}

// ---------------- per-point projection + stable top-4 ----------------
__global__ __launch_bounds__(128)
void proj_topk_kernel(const float* __restrict__ xyz, int M)
{
    int m = blockIdx.x * blockDim.x + threadIdx.x;
    if (m >= M) return;
    float X = xyz[3*m+0], Y = xyz[3*m+1], Z = xyz[3*m+2];
    float W = g_scal[0], H = g_scal[1];

    float bs[KSEL] = {-1.f,-1.f,-1.f,-1.f};
    int   bi[KSEL] = {1000,1000,1000,1000};
    float bu[KSEL], bv[KSEL], bz[KSEL];
    #pragma unroll
    for (int q = 0; q < KSEL; q++) { bu[q]=0; bv[q]=0; bz[q]=0; }

    for (int cam = 0; cam < TVC; cam++) {
        const float* P = g_P + cam*12;
        float uw = P[0]*X + P[1]*Y + P[2] *Z + P[3];
        float vw = P[4]*X + P[5]*Y + P[6] *Z + P[7];
        float z  = P[8]*X + P[9]*Y + P[10]*Z + P[11];
        float wd = fmaxf(z, 1e-6f);
        float u = uw / wd, v = vw / wd;
        bool vis = (z > 1e-4f) && (u >= 0.f) && (u < W) && (v >= 0.f) && (v < H);
        float score = vis ? (1.0f / (fmaxf(z, 0.1f) + 1e-6f)) : 0.0f;
        #pragma unroll
        for (int slot = 0; slot < KSEL; slot++) {
            bool better = (score > bs[slot]) || (score == bs[slot] && cam < bi[slot]);
            if (better) {
                for (int q = KSEL-1; q > slot; q--) {
                    bs[q]=bs[q-1]; bi[q]=bi[q-1]; bu[q]=bu[q-1]; bv[q]=bv[q-1]; bz[q]=bz[q-1];
                }
                bs[slot]=score; bi[slot]=cam; bu[slot]=u; bv[slot]=v; bz[slot]=z;
                break;
            }
        }
    }
    #pragma unroll
    for (int q = 0; q < KSEL; q++) {
        int t = m*KSEL + q;
        g_selcam[t] = bi[q];
        g_selu[t] = bu[q]; g_selv[t] = bv[q]; g_selz[t] = bz[q];
    }
}

// Activation split: h = RN(v), m8 = RN(h/8 + 4*(v-h))
__device__ __forceinline__ void split_store(__half* hp, __half* mp, size_t idx, float v) {
    __half h = __float2half_rn(v);
    float hf = __half2float(h);
    float l  = v - hf;
    hp[idx] = h;
    mp[idx] = __float2half_rn(hf*0.125f + 4.0f*l);
}

// ---------------- bilinear gather + pos feats -> xin h/m8 [Ntok,96] ----------------
__global__ __launch_bounds__(256)
void gather_kernel(const float* __restrict__ feat,
                   const float* __restrict__ view_emb,
                   const float* __restrict__ pos_w,
                   const float* __restrict__ pos_b,
                   int Ntok)
{
    int wid  = (blockIdx.x * blockDim.x + threadIdx.x) >> 5;
    int lane = threadIdx.x & 31;
    if (wid >= Ntok) return;

    int   cam = g_selcam[wid];
    float u = g_selu[wid], v = g_selv[wid], z = g_selz[wid];
    float uf = u * g_scal[2], vf = v * g_scal[3];
    float x0f = floorf(uf), y0f = floorf(vf);
    float fx = uf - x0f, fy = vf - y0f;
    int x0 = (int)x0f, y0 = (int)y0f;
    float w00 = (1.f-fx)*(1.f-fy);
    float w01 = fx*(1.f-fy);
    float w10 = (1.f-fx)*fy;
    float w11 = fx*fy;
    float zm  = (z > 1e-4f) ? 1.0f : 0.0f;

    float s0 = 0.f, s1 = 0.f;
    #pragma unroll
    for (int dy = 0; dy < 2; dy++) {
        #pragma unroll
        for (int dx = 0; dx < 2; dx++) {
            int xi = x0 + dx, yi = y0 + dy;
            bool val = (xi >= 0) && (xi < WP) && (yi >= 0) && (yi < HP);
            int xc = min(max(xi, 0), WP-1);
            int yc = min(max(yi, 0), HP-1);
            size_t base = (((size_t)cam*HP + yc)*WP + xc) * C_;
            float w = dy ? (dx ? w11 : w10) : (dx ? w01 : w00);
            float f0 = feat[base + lane];
            float f1 = feat[base + lane + 32];
            if (!val) { f0 = 0.f; f1 = 0.f; }
            s0 += w * f0;
            s1 += w * f1;
        }
    }
    size_t xb = (size_t)wid * 96;
    split_store(g_xh, g_xl, xb + lane,      s0 * zm);
    split_store(g_xh, g_xl, xb + 32 + lane, s1 * zm);

    int tdx = cam / V_;
    int vdx = cam % V_;
    int vmin = min(vdx, 63);
    float acc = pos_b[lane];
    #pragma unroll
    for (int i = 0; i < TE; i++)
        acc += g_temb[tdx*TE + i] * pos_w[i*32 + lane];
    #pragma unroll
    for (int i = 0; i < VE; i++)
        acc += view_emb[vmin*VE + i] * pos_w[(TE + i)*32 + lane];
    split_store(g_xh, g_xl, xb + 64 + lane, acc);
}

// ---------------- shared helpers ----------------
__device__ __forceinline__ void mma16816(float* c, const uint32_t* a, uint32_t b0, uint32_t b1) {
    asm volatile(
        "mma.sync.aligned.m16n8k16.row.col.f32.f16.f16.f32 "
        "{%0,%1,%2,%3}, {%4,%5,%6,%7}, {%8,%9}, {%0,%1,%2,%3};\n"
        : "+f"(c[0]), "+f"(c[1]), "+f"(c[2]), "+f"(c[3])
        : "r"(a[0]), "r"(a[1]), "r"(a[2]), "r"(a[3]), "r"(b0), "r"(b1));
}
__device__ __forceinline__ void ldsm4(uint32_t* r, uint32_t addr) {
    asm volatile("ldmatrix.sync.aligned.m8n8.x4.shared.b16 {%0,%1,%2,%3}, [%4];"
        : "=r"(r[0]), "=r"(r[1]), "=r"(r[2]), "=r"(r[3]) : "r"(addr));
}
__device__ __forceinline__ void cpa16(uint32_t dst, const void* src, int sz) {
    asm volatile("cp.async.cg.shared.global [%0], [%1], 16, %2;\n" :: "r"(dst), "l"(src), "r"(sz));
}
__device__ __forceinline__ void cp_commit() { asm volatile("cp.async.commit_group;\n"); }
__device__ __forceinline__ void cp_wait0()  { asm volatile("cp.async.wait_group 0;\n"); }

extern __shared__ __half s_dyn[];

// ---- 2-MMA compensated GEMM, BM=64 BN=256 BK=64, unified h/m loop, 1 sync/tile ----
// D = (31/32)*sum(Ah*Bh) + sum(Am8*Bm4). mode: 1=relu, 2=fp32 out, 4=half out.
#define SKB 72                              // halves per smem row (144 B)
#define GA_B (64*SKB*2)                     // 9216  (A: 64 rows)
#define GB_B (256*SKB*2)                    // 36864 (B: 256 rows)
#define GST  (GA_B + GB_B)                  // 46080 per stage
#define GTOT (2*GST)                        // 92160
#define FRED2 GTOT                          // LN red buffer after stages
#define FTOT2 (FRED2 + 64*4*8)              // 94208

__global__ __launch_bounds__(256, 2)
void gemm_big(const __half* __restrict__ Ah, const __half* __restrict__ Am,
              const __half* __restrict__ Bh, const __half* __restrict__ Bm,
              const float* __restrict__ bias, float* __restrict__ C,
              __half* __restrict__ Ch, __half* __restrict__ Cm,
              int N, int Kd, int Nout, int mode)
{
    int bm = blockIdx.y * 64;
    int bn = blockIdx.x * 256;
    int tid = threadIdx.x;
    int wid = tid >> 5, lane = tid & 31;
    int g = lane >> 2, tc = lane & 3;
    int wr = wid >> 2;
    int wc = wid & 3;
    uint32_t sb = (uint32_t)__cvta_generic_to_shared(s_dyn);

    uint32_t a_off[2];
    #pragma unroll
    for (int i = 0; i < 2; i++)
        a_off[i] = (uint32_t)(((wr*32 + i*16 + (lane & 15)) * SKB + ((lane >> 4) << 3)) * 2);
    uint32_t b_off[4];
    #pragma unroll
    for (int jp = 0; jp < 4; jp++)
        b_off[jp] = (uint32_t)(((wc*64 + jp*16 + (lane & 7) + ((lane >> 4) << 3)) * SKB
                                + (((lane >> 3) & 1) << 3)) * 2);

    float acc[2][8][4];
    #pragma unroll
    for (int i = 0; i < 2; i++)
        #pragma unroll
        for (int j = 0; j < 8; j++)
            #pragma unroll
            for (int r = 0; r < 4; r++) acc[i][j][r] = 0.f;

    const int NTt = (Kd + 63) >> 6;

    auto load_stage = [&](int st, int k0, const __half* Ap, const __half* Bp) {
        #pragma unroll
        for (int r = 0; r < 2; r++) {
            int id  = tid + r*256;
            int row = id >> 3, seg = id & 7;
            uint32_t d = sb + st*GST + row*(SKB*2) + seg*16;
            int gr = bm + row;
            int kk = k0 + seg*8;
            bool ok = (gr < N) && (kk + 8 <= Kd);
            cpa16(d, Ap + (size_t)(ok ? gr : 0) * Kd + (ok ? kk : 0), ok ? 16 : 0);
        }
        #pragma unroll
        for (int r = 0; r < 8; r++) {
            int id  = tid + r*256;
            int row = id >> 3, seg = id & 7;
            uint32_t d = sb + st*GST + GA_B + row*(SKB*2) + seg*16;
            int gn = bn + row;
            int kk = k0 + seg*8;
            bool ok = (gn < Nout) && (kk + 8 <= Kd);
            cpa16(d, Bp + (size_t)(ok ? gn : 0) * Kd + (ok ? kk : 0), ok ? 16 : 0);
        }
        cp_commit();
    };

    load_stage(0, 0, Ah, Bh);

    const int NT2 = 2 * NTt;
    for (int t = 0; t < NT2; t++) {
        cp_wait0();
        __syncthreads();
        int tn = t + 1;
        if (tn < NT2) {
            bool m2 = tn >= NTt;
            load_stage(tn & 1, (m2 ? tn - NTt : tn) * 64, m2 ? Am : Ah, m2 ? Bm : Bh);
        }
        if (t == NTt) {
            #pragma unroll
            for (int i = 0; i < 2; i++)
                #pragma unroll
                for (int j = 0; j < 8; j++)
                    #pragma unroll
                    for (int r = 0; r < 4; r++) acc[i][j][r] *= (31.0f/32.0f);
        }

        uint32_t sa  = sb + (t & 1)*GST;
        uint32_t sbb = sa + GA_B;

        #pragma unroll
        for (int kb = 0; kb < 64; kb += 16) {
            uint32_t kbB = kb * 2;
            uint32_t ah[2][4];
            #pragma unroll
            for (int i = 0; i < 2; i++)
                ldsm4(ah[i], sa + a_off[i] + kbB);
            #pragma unroll
            for (int jp = 0; jp < 4; jp++) {
                uint32_t bh[4];
                ldsm4(bh, sbb + b_off[jp] + kbB);
                #pragma unroll
                for (int jj = 0; jj < 2; jj++) {
                    int j = jp*2 + jj;
                    #pragma unroll
                    for (int i = 0; i < 2; i++)
                        mma16816(acc[i][j], ah[i], bh[jj*2], bh[jj*2+1]);
                }
            }
        }
    }

    bool relu  = mode & 1;
    bool wfp   = mode & 2;
    bool whalf = mode & 4;
    #pragma unroll
    for (int j = 0; j < 8; j++) {
        int col = bn + wc*64 + j*8 + tc*2;
        if (col >= Nout) continue;
        float bx = bias[col], by = bias[col+1];
        #pragma unroll
        for (int i = 0; i < 2; i++) {
            int r0 = bm + wr*32 + i*16 + g;
            int r1 = r0 + 8;
            float v0 = acc[i][j][0] + bx;
            float v1 = acc[i][j][1] + by;
            float v2 = acc[i][j][2] + bx;
            float v3 = acc[i][j][3] + by;
            if (relu) {
                v0 = fmaxf(v0, 0.f); v1 = fmaxf(v1, 0.f);
                v2 = fmaxf(v2, 0.f); v3 = fmaxf(v3, 0.f);
            }
            if (r0 < N) {
                size_t o = (size_t)r0*Nout + col;
                if (wfp) { C[o] = v0; C[o+1] = v1; }
                if (whalf) {
                    __half h0 = __float2half_rn(v0), h1 = __float2half_rn(v1);
                    float f0 = __half2float(h0), f1 = __half2float(h1);
                    *(__half2*)(Ch + o) = __halves2half2(h0, h1);
                    *(__half2*)(Cm + o) = __halves2half2(
                        __float2half_rn(f0*0.125f + 4.0f*(v0 - f0)),
                        __float2half_rn(f1*0.125f + 4.0f*(v1 - f1)));
                }
            }
            if (r1 < N) {
                size_t o = (size_t)r1*Nout + col;
                if (wfp) { C[o] = v2; C[o+1] = v3; }
                if (whalf) {
                    __half h2 = __float2half_rn(v2), h3 = __float2half_rn(v3);
                    float f2 = __half2float(h2), f3 = __half2float(h3);
                    *(__half2*)(Ch + o) = __halves2half2(h2, h3);
                    *(__half2*)(Cm + o) = __halves2half2(
                        __float2half_rn(f2*0.125f + 4.0f*(v2 - f2)),
                        __float2half_rn(f3*0.125f + 4.0f*(v3 - f3)));
                }
            }
        }
    }
}

// ---------------- fused GEMM + residual + LayerNorm (Nout=256), same geometry ----------------
__global__ __launch_bounds__(256, 2)
void gemm_ln(const __half* __restrict__ Ah, const __half* __restrict__ Am,
             const __half* __restrict__ Bh, const __half* __restrict__ Bm,
             const float* __restrict__ bias,
             const float* __restrict__ lns, const float* __restrict__ lnb,
             float* __restrict__ Hres, __half* __restrict__ Ch, __half* __restrict__ Cm,
             int N, int Kd)
{
    int bm = blockIdx.x * 64;
    int tid = threadIdx.x;
    int wid = tid >> 5, lane = tid & 31;
    int g = lane >> 2, tc = lane & 3;
    int wr = wid >> 2;
    int wc = wid & 3;
    uint32_t sb = (uint32_t)__cvta_generic_to_shared(s_dyn);
    float2* red = (float2*)((char*)s_dyn + FRED2);

    uint32_t a_off[2];
    #pragma unroll
    for (int i = 0; i < 2; i++)
        a_off[i] = (uint32_t)(((wr*32 + i*16 + (lane & 15)) * SKB + ((lane >> 4) << 3)) * 2);
    uint32_t b_off[4];
    #pragma unroll
    for (int jp = 0; jp < 4; jp++)
        b_off[jp] = (uint32_t)(((wc*64 + jp*16 + (lane & 7) + ((lane >> 4) << 3)) * SKB
                                + (((lane >> 3) & 1) << 3)) * 2);

    float acc[2][8][4];
    #pragma unroll
    for (int i = 0; i < 2; i++)
        #pragma unroll
        for (int j = 0; j < 8; j++)
            #pragma unroll
            for (int r = 0; r < 4; r++) acc[i][j][r] = 0.f;

    const int NTt = (Kd + 63) >> 6;

    auto load_stage = [&](int st, int k0, const __half* Ap, const __half* Bp) {
        #pragma unroll
        for (int r = 0; r < 2; r++) {
            int id  = tid + r*256;
            int row = id >> 3, seg = id & 7;
            uint32_t d = sb + st*GST + row*(SKB*2) + seg*16;
            int gr = bm + row;
            int kk = k0 + seg*8;
            bool ok = (gr < N) && (kk + 8 <= Kd);
            cpa16(d, Ap + (size_t)(ok ? gr : 0) * Kd + (ok ? kk : 0), ok ? 16 : 0);
        }
        #pragma unroll
        for (int r = 0; r < 8; r++) {
            int id  = tid + r*256;
            int row = id >> 3, seg = id & 7;
            uint32_t d = sb + st*GST + GA_B + row*(SKB*2) + seg*16;
            int kk = k0 + seg*8;
            bool ok = (kk + 8 <= Kd);
            cpa16(d, Bp + (size_t)row * Kd + (ok ? kk : 0), ok ? 16 : 0);
        }
        cp_commit();
    };

    load_stage(0, 0, Ah, Bh);

    const int NT2 = 2 * NTt;
    for (int t = 0; t < NT2; t++) {
        cp_wait0();
        __syncthreads();
        int tn = t + 1;
        if (tn < NT2) {
            bool m2 = tn >= NTt;
            load_stage(tn & 1, (m2 ? tn - NTt : tn) * 64, m2 ? Am : Ah, m2 ? Bm : Bh);
        }
        if (t == NTt) {
            #pragma unroll
            for (int i = 0; i < 2; i++)
                #pragma unroll
                for (int j = 0; j < 8; j++)
                    #pragma unroll
                    for (int r = 0; r < 4; r++) acc[i][j][r] *= (31.0f/32.0f);
        }

        uint32_t sa  = sb + (t & 1)*GST;
        uint32_t sbb = sa + GA_B;

        #pragma unroll
        for (int kb = 0; kb < 64; kb += 16) {
            uint32_t kbB = kb * 2;
            uint32_t ah[2][4];
            #pragma unroll
            for (int i = 0; i < 2; i++)
                ldsm4(ah[i], sa + a_off[i] + kbB);
            #pragma unroll
            for (int jp = 0; jp < 4; jp++) {
                uint32_t bh[4];
                ldsm4(bh, sbb + b_off[jp] + kbB);
                #pragma unroll
                for (int jj = 0; jj < 2; jj++) {
                    int j = jp*2 + jj;
                    #pragma unroll
                    for (int i = 0; i < 2; i++)
                        mma16816(acc[i][j], ah[i], bh[jj*2], bh[jj*2+1]);
                }
            }
        }
    }
    __syncthreads();   // all compute done before red-buffer reuse ordering below

    // ---- epilogue: x = h_old + (acc + bias); per-row LN over 256 cols ----
    int colw = wc*64;
    #pragma unroll
    for (int i = 0; i < 2; i++) {
        int rbase = wr*32 + i*16 + g;
        #pragma unroll
        for (int hhf = 0; hhf < 2; hhf++) {
            int rl = rbase + hhf*8;
            int grow = bm + rl;
            bool rv = grow < N;
            const float* hrow = Hres + (size_t)grow*256;
            float s1 = 0.f, s2 = 0.f;
            #pragma unroll
            for (int j = 0; j < 8; j++) {
                int col = colw + j*8 + tc*2;
                float2 hv = rv ? *(const float2*)(hrow + col) : make_float2(0.f, 0.f);
                float x0 = acc[i][j][hhf*2+0] + bias[col]   + hv.x;
                float x1 = acc[i][j][hhf*2+1] + bias[col+1] + hv.y;
                acc[i][j][hhf*2+0] = x0;
                acc[i][j][hhf*2+1] = x1;
                s1 += x0 + x1;
                s2 += x0*x0 + x1*x1;
            }
            s1 += __shfl_xor_sync(0xFFFFFFFFu, s1, 1);
            s1 += __shfl_xor_sync(0xFFFFFFFFu, s1, 2);
            s2 += __shfl_xor_sync(0xFFFFFFFFu, s2, 1);
            s2 += __shfl_xor_sync(0xFFFFFFFFu, s2, 2);
            if (tc == 0) red[(rl << 2) + wc] = make_float2(s1, s2);
        }
    }
    __syncthreads();
    #pragma unroll
    for (int i = 0; i < 2; i++) {
        int rbase = wr*32 + i*16 + g;
        #pragma unroll
        for (int hhf = 0; hhf < 2; hhf++) {
            int rl = rbase + hhf*8;
            int grow = bm + rl;
            if (grow >= N) continue;
            float2 t0 = red[(rl<<2)+0], t1 = red[(rl<<2)+1];
            float2 t2 = red[(rl<<2)+2], t3 = red[(rl<<2)+3];
            float tS  = t0.x + t1.x + t2.x + t3.x;
            float tS2 = t0.y + t1.y + t2.y + t3.y;
            float mu  = tS * (1.0f/256.0f);
            float var = tS2 * (1.0f/256.0f) - mu*mu;
            float rinv = rsqrtf(var + 1e-5f);
            float* hrow = Hres + (size_t)grow*256;
            size_t ob = (size_t)grow*256;
            #pragma unroll
            for (int j = 0; j < 8; j++) {
                int col = colw + j*8 + tc*2;
                float y0 = (acc[i][j][hhf*2+0] - mu)*rinv*lns[col]   + lnb[col];
                float y1 = (acc[i][j][hhf*2+1] - mu)*rinv*lns[col+1] + lnb[col+1];
                *(float2*)(hrow + col) = make_float2(y0, y1);
                __half h0 = __float2half_rn(y0), h1 = __float2half_rn(y1);
                float f0 = __half2float(h0), f1 = __half2float(h1);
                *(__half2*)(Ch + ob + col) = __halves2half2(h0, h1);
                *(__half2*)(Cm + ob + col) = __halves2half2(
                    __float2half_rn(f0*0.125f + 4.0f*(y0 - f0)),
                    __float2half_rn(f1*0.125f + 4.0f*(y1 - f1)));
            }
        }
    }
}

// ---------------- attention over 4 tokens, 8 heads, Dh=32 -> o h/m8 ----------------
__global__ __launch_bounds__(256)
void attn_kernel(int M)
{
    int m = blockIdx.x;
    if (m >= M) return;
    int h = threadIdx.x >> 5;
    int lane = threadIdx.x & 31;
    const float* qkv = g_qkv + (size_t)m * KSEL * 768;

    float q[4], k[4], v[4];
    #pragma unroll
    for (int j = 0; j < 4; j++) {
        q[j] = qkv[(size_t)j*768 +        h*32 + lane];
        k[j] = qkv[(size_t)j*768 + 256  + h*32 + lane];
        v[j] = qkv[(size_t)j*768 + 512  + h*32 + lane];
    }
    float s[16];
    #pragma unroll
    for (int i = 0; i < 4; i++)
        #pragma unroll
        for (int j = 0; j < 4; j++)
            s[i*4+j] = q[i] * k[j];
    #pragma unroll
    for (int off = 16; off > 0; off >>= 1)
        #pragma unroll
        for (int x = 0; x < 16; x++)
            s[x] += __shfl_xor_sync(0xFFFFFFFFu, s[x], off);

    const float scale = 0.17677669529663687f;
    float a[16];
    #pragma unroll
    for (int i = 0; i < 4; i++) {
        float s0 = s[i*4+0]*scale, s1 = s[i*4+1]*scale;
        float s2 = s[i*4+2]*scale, s3 = s[i*4+3]*scale;
        float mx = fmaxf(fmaxf(s0, s1), fmaxf(s2, s3));
        float e0 = expf(s0-mx), e1 = expf(s1-mx), e2 = expf(s2-mx), e3 = expf(s3-mx);
        float r = 1.0f / (e0+e1+e2+e3);
        a[i*4+0] = e0*r; a[i*4+1] = e1*r; a[i*4+2] = e2*r; a[i*4+3] = e3*r;
    }
    size_t ob = (size_t)m * KSEL * 256;
    #pragma unroll
    for (int i = 0; i < 4; i++) {
        float oi = a[i*4+0]*v[0] + a[i*4+1]*v[1] + a[i*4+2]*v[2] + a[i*4+3]*v[3];
        split_store(g_oh, g_ol, ob + (size_t)i*256 + h*32 + lane, oi);
    }
}

// ---------------- mean over the 4 tokens -> h/m8 ----------------
__global__ __launch_bounds__(256)
void mean_kernel(int M)
{
    int idx = blockIdx.x * blockDim.x + threadIdx.x;
    if (idx >= M*256) return;
    int m = idx >> 8, c = idx & 255;
    const float* hp = g_h + (size_t)m*4*256 + c;
    split_store(g_mh, g_ml, idx, 0.25f * (hp[0] + hp[256] + hp[512] + hp[768]));
}

// ---------------- host launch ----------------
extern "C" void kernel_launch(void* const* d_in, const int* in_sizes, int n_in,
                              void* d_out, int out_size)
{
    const float* xyz      = (const float*)d_in[0];
    const float* feat     = (const float*)d_in[1];
    const float* poses    = (const float*)d_in[2];
    const float* intr     = (const float*)d_in[3];
    const int*   time_ids = (const int*)  d_in[4];
    const float* view_emb = (const float*)d_in[5];
    const float* pos_w    = (const float*)d_in[6];
    const float* pos_b    = (const float*)d_in[7];
    const float* fp_w     = (const float*)d_in[8];
    const float* fp_b     = (const float*)d_in[9];
    const float* qkv_w    = (const float*)d_in[10];
    const float* qkv_b    = (const float*)d_in[11];
    const float* ao_w     = (const float*)d_in[12];
    const float* ao_b     = (const float*)d_in[13];
    const float* ln1_s    = (const float*)d_in[14];
    const float* ln1_b    = (const float*)d_in[15];
    const float* ff1_w    = (const float*)d_in[16];
    const float* ff1_b    = (const float*)d_in[17];
    const float* ff2_w    = (const float*)d_in[18];
    const float* ff2_b    = (const float*)d_in[19];
    const float* ln2_s    = (const float*)d_in[20];
    const float* ln2_b    = (const float*)d_in[21];
    const float* out_w    = (const float*)d_in[22];
    const float* out_b    = (const float*)d_in[23];

    int M    = in_sizes[0] / 3;
    int Ntok = M * KSEL;
    int T    = in_sizes[4];

    float *ph, *pqkv;
    __half *pxh,*pxl,*phh,*phl,*poh,*pol,*pfh,*pfl,*pmh,*pml,*pwh,*pwl;
    cudaGetSymbolAddress((void**)&ph,    g_h);
    cudaGetSymbolAddress((void**)&pqkv,  g_qkv);
    cudaGetSymbolAddress((void**)&pxh, g_xh); cudaGetSymbolAddress((void**)&pxl, g_xl);
    cudaGetSymbolAddress((void**)&phh, g_hh); cudaGetSymbolAddress((void**)&phl, g_hl);
    cudaGetSymbolAddress((void**)&poh, g_oh); cudaGetSymbolAddress((void**)&pol, g_ol);
    cudaGetSymbolAddress((void**)&pfh, g_fh); cudaGetSymbolAddress((void**)&pfl, g_fl);
    cudaGetSymbolAddress((void**)&pmh, g_mh); cudaGetSymbolAddress((void**)&pml, g_ml);
    cudaGetSymbolAddress((void**)&pwh, g_wh); cudaGetSymbolAddress((void**)&pwl, g_wl);

    cudaFuncSetAttribute(gemm_big, cudaFuncAttributeMaxDynamicSharedMemorySize, GTOT);
    cudaFuncSetAttribute(gemm_ln,  cudaFuncAttributeMaxDynamicSharedMemorySize, FTOT2);

    const long long off_fp   = 0;
    const long long off_qkv0 = off_fp   + 24576;
    const long long off_qkv1 = off_qkv0 + 196608;
    const long long off_ao0  = off_qkv1 + 196608;
    const long long off_ao1  = off_ao0  + 65536;
    const long long off_ff10 = off_ao1  + 65536;
    const long long off_ff11 = off_ff10 + 131072;
    const long long off_ff20 = off_ff11 + 131072;
    const long long off_ff21 = off_ff20 + 131072;
    const long long off_out  = off_ff21 + 131072;

    WTab tab;
    tab.src[0]=fp_w;            tab.off[0]=off_fp;   tab.kd[0]=96;  tab.nout[0]=256;
    tab.src[1]=qkv_w;           tab.off[1]=off_qkv0; tab.kd[1]=256; tab.nout[1]=768;
    tab.src[2]=qkv_w+256*768;   tab.off[2]=off_qkv1; tab.kd[2]=256; tab.nout[2]=768;
    tab.src[3]=ao_w;            tab.off[3]=off_ao0;  tab.kd[3]=256; tab.nout[3]=256;
    tab.src[4]=ao_w+256*256;    tab.off[4]=off_ao1;  tab.kd[4]=256; tab.nout[4]=256;
    tab.src[5]=ff1_w;           tab.off[5]=off_ff10; tab.kd[5]=256; tab.nout[5]=512;
    tab.src[6]=ff1_w+256*512;   tab.off[6]=off_ff11; tab.kd[6]=256; tab.nout[6]=512;
    tab.src[7]=ff2_w;           tab.off[7]=off_ff20; tab.kd[7]=512; tab.nout[7]=256;
    tab.src[8]=ff2_w+512*256;   tab.off[8]=off_ff21; tab.kd[8]=512; tab.nout[8]=256;
    tab.src[9]=out_w;           tab.off[9]=off_out;  tab.kd[9]=256; tab.nout[9]=64;
    wconv_all<<<dim3(768, 10), 256>>>(tab, pwh, pwl);

    setup_kernel<<<1, 32>>>(poses, intr, time_ids, T);
    proj_topk_kernel<<<(M + 127)/128, 128>>>(xyz, M);
    gather_kernel<<<(Ntok*32 + 255)/256, 256>>>(feat, view_emb, pos_w, pos_b, Ntok);

    auto gemm = [&](const __half* Ahp, const __half* Amp, long long woff,
                    const float* bias, float* C, __half* Ch, __half* Cm,
                    int N, int Kd, int Nout, int mode) {
        dim3 grid((Nout + 255)/256, (N + 63)/64);
        gemm_big<<<grid, 256, GTOT>>>(Ahp, Amp, pwh + woff, pwl + woff,
                                      bias, C, Ch, Cm, N, Kd, Nout, mode);
    };

    // fp: xin -> h (fp32 + halves)
    gemm(pxh, pxl, off_fp, fp_b, ph, phh, phl, Ntok, 96, 256, 2|4);

    const long long qoff[2]  = {off_qkv0, off_qkv1};
    const long long aoff[2]  = {off_ao0,  off_ao1};
    const long long f1off[2] = {off_ff10, off_ff11};
    const long long f2off[2] = {off_ff20, off_ff21};
    int gln = (Ntok + 63)/64;
    for (int l = 0; l < 2; l++) {
        gemm(phh, phl, qoff[l], qkv_b + l*768, pqkv, nullptr, nullptr, Ntok, 256, 768, 2);
        attn_kernel<<<M, 256>>>(M);
        gemm_ln<<<gln, 256, FTOT2>>>(poh, pol, pwh + aoff[l], pwl + aoff[l],
                                     ao_b + l*256, ln1_s + l*256, ln1_b + l*256,
                                     ph, phh, phl, Ntok, 256);
        gemm(phh, phl, f1off[l], ff1_b + l*512, nullptr, pfh, pfl, Ntok, 256, 512, 4|1);
        gemm_ln<<<gln, 256, FTOT2>>>(pfh, pfl, pwh + f2off[l], pwl + f2off[l],
                                     ff2_b + l*256, ln2_s + l*256, ln2_b + l*256,
                                     ph, phh, phl, Ntok, 512);
    }

    mean_kernel<<<(M*256 + 255)/256, 256>>>(M);
    gemm(pmh, pml, off_out, out_b, (float*)d_out, nullptr, nullptr, M, 256, 64, 2);
}

// round 16
// speedup vs baseline: 1.0203x; 1.0203x over previous
// v16: identical to v15 (resubmit; broker flaked) — BM=128 BN=128 BK=64, 1 sync/tile
#include <cuda_runtime.h>
#include <cuda_fp16.h>
#include <math.h>
#include <stdint.h>

// ---------------- problem constants ----------------
#define T_    4
#define V_    8
#define TVC   32
#define HP    64
#define WP    64
#define C_    64
#define KSEL  4
#define HID   256
#define TE    32
#define VE    16
#define MAXM  50000
#define MAXTOK (MAXM*KSEL)

// ---------------- scratch ----------------
__device__ float g_P[TVC*12];
__device__ float g_scal[4];
__device__ float g_temb[T_*TE];
__device__ int   g_selcam[MAXTOK];
__device__ float g_selu[MAXTOK];
__device__ float g_selv[MAXTOK];
__device__ float g_selz[MAXTOK];

// fp32 intermediates
__device__ float g_h   [(size_t)MAXTOK*256];
__device__ float g_qkv [(size_t)MAXTOK*768];

// half (h, m/8) activation buffers
__device__ __half g_xh[(size_t)MAXTOK*96],  g_xl[(size_t)MAXTOK*96];
__device__ __half g_hh[(size_t)MAXTOK*256], g_hl[(size_t)MAXTOK*256];
__device__ __half g_oh[(size_t)MAXTOK*256], g_ol[(size_t)MAXTOK*256];
__device__ __half g_fh[(size_t)MAXTOK*512], g_fl[(size_t)MAXTOK*512];
__device__ __half g_mh[(size_t)MAXM*256],   g_ml[(size_t)MAXM*256];

// preconverted transposed weights [Nout][Kd], (h, m/4)
#define WTOTAL 1089536
__device__ __half g_wh[WTOTAL], g_wl[WTOTAL];

// ---------------- setup ----------------
__global__ void setup_kernel(const float* __restrict__ poses,
                             const float* __restrict__ intr,
                             const int*   __restrict__ time_ids,
                             int T)
{
    int n = threadIdx.x;
    if (n < TVC) {
        double a[4][8];
        for (int r = 0; r < 4; r++)
            for (int c = 0; c < 4; c++) {
                a[r][c]   = (double)poses[n*16 + r*4 + c];
                a[r][4+c] = (r == c) ? 1.0 : 0.0;
            }
        for (int col = 0; col < 4; col++) {
            int piv = col;
            for (int r = col+1; r < 4; r++)
                if (fabs(a[r][col]) > fabs(a[piv][col])) piv = r;
            if (piv != col)
                for (int c = 0; c < 8; c++) { double t = a[col][c]; a[col][c] = a[piv][c]; a[piv][c] = t; }
            double dv = a[col][col];
            for (int c = 0; c < 8; c++) a[col][c] /= dv;
            for (int r = 0; r < 4; r++) if (r != col) {
                double f = a[r][col];
                for (int c = 0; c < 8; c++) a[r][c] -= f * a[col][c];
            }
        }
        double Km[9];
        for (int i = 0; i < 9; i++) Km[i] = (double)intr[n*9 + i];
        for (int r = 0; r < 3; r++)
            for (int c = 0; c < 4; c++) {
                double s = 0.0;
                for (int j = 0; j < 3; j++) s += Km[r*3 + j] * a[j][4 + c];
                g_P[n*12 + r*4 + c] = (float)s;
            }
    }
    if (n == 0) {
        float cx = intr[2], cy = intr[5];
        float W = 2.0f*cx, H = 2.0f*cy;
        g_scal[0] = W; g_scal[1] = H;
        g_scal[2] = (float)WP / fmaxf(1.0f, W);
        g_scal[3] = (float)HP / fmaxf(1.0f, H);
        int tmin = time_ids[0], tmax = time_ids[0];
        for (int t = 1; t < T; t++) {
            int v = time_ids[t];
            if (v < tmin) tmin = v;
            if (v > tmax) tmax = v;
        }
        if (tmax < tmin + 1) tmax = tmin + 1;
        for (int t = 0; t < T; t++) {
            double tn = (double)(time_ids[t] - tmin) / (double)(tmax - tmin);
            for (int i = 0; i < TE/2; i++) {
                double f  = exp(8.0 * (double)i / (double)(TE/2 - 1));
                double ph = tn * f;
                g_temb[t*TE + i]        = (float)sin(ph);
                g_temb[t*TE + TE/2 + i] = (float)cos(ph);
            }
        }
    }
}

// ---------------- single-launch weight convert + transpose ----------------
struct WTab {
    const float* src[10];
    long long    off[10];
    int          kd[10];
    int          nout[10];
};
__global__ __launch_bounds__(256)
void wconv_all(WTab tab, __half* __restrict__ Wh, __half* __restrict__ Wl)
{
    int mi  = blockIdx.y;
    int idx = blockIdx.x * blockDim.x + threadIdx.x;
    int Kd = tab.kd[mi], Nout = tab.nout[mi];
    if (idx >= Kd * Nout) return;
    int n = idx / Kd, k = idx - n*Kd;
    float w = tab.src[mi][(size_t)k*Nout + n];
    __half h = __float2half_rn(w);
    float hf = __half2float(h);
    float l  = w - hf;
    size_t o = (size_t)tab.off[mi] + idx;
    Wh[o] = h;
    Wl[o] = __float2half_rn(hf*0.25f + 8.0f*l);
}

// ---------------- per-point projection + stable top-4 ----------------
__global__ __launch_bounds__(128)
void proj_topk_kernel(const float* __restrict__ xyz, int M)
{
    int m = blockIdx.x * blockDim.x + threadIdx.x;
    if (m >= M) return;
    float X = xyz[3*m+0], Y = xyz[3*m+1], Z = xyz[3*m+2];
    float W = g_scal[0], H = g_scal[1];

    float bs[KSEL] = {-1.f,-1.f,-1.f,-1.f};
    int   bi[KSEL] = {1000,1000,1000,1000};
    float bu[KSEL], bv[KSEL], bz[KSEL];
    #pragma unroll
    for (int q = 0; q < KSEL; q++) { bu[q]=0; bv[q]=0; bz[q]=0; }

    for (int cam = 0; cam < TVC; cam++) {
        const float* P = g_P + cam*12;
        float uw = P[0]*X + P[1]*Y + P[2] *Z + P[3];
        float vw = P[4]*X + P[5]*Y + P[6] *Z + P[7];
        float z  = P[8]*X + P[9]*Y + P[10]*Z + P[11];
        float wd = fmaxf(z, 1e-6f);
        float u = uw / wd, v = vw / wd;
        bool vis = (z > 1e-4f) && (u >= 0.f) && (u < W) && (v >= 0.f) && (v < H);
        float score = vis ? (1.0f / (fmaxf(z, 0.1f) + 1e-6f)) : 0.0f;
        #pragma unroll
        for (int slot = 0; slot < KSEL; slot++) {
            bool better = (score > bs[slot]) || (score == bs[slot] && cam < bi[slot]);
            if (better) {
                for (int q = KSEL-1; q > slot; q--) {
                    bs[q]=bs[q-1]; bi[q]=bi[q-1]; bu[q]=bu[q-1]; bv[q]=bv[q-1]; bz[q]=bz[q-1];
                }
                bs[slot]=score; bi[slot]=cam; bu[slot]=u; bv[slot]=v; bz[slot]=z;
                break;
            }
        }
    }
    #pragma unroll
    for (int q = 0; q < KSEL; q++) {
        int t = m*KSEL + q;
        g_selcam[t] = bi[q];
        g_selu[t] = bu[q]; g_selv[t] = bv[q]; g_selz[t] = bz[q];
    }
}

// Activation split: h = RN(v), m8 = RN(h/8 + 4*(v-h))
__device__ __forceinline__ void split_store(__half* hp, __half* mp, size_t idx, float v) {
    __half h = __float2half_rn(v);
    float hf = __half2float(h);
    float l  = v - hf;
    hp[idx] = h;
    mp[idx] = __float2half_rn(hf*0.125f + 4.0f*l);
}

// ---------------- bilinear gather + pos feats -> xin h/m8 [Ntok,96] ----------------
__global__ __launch_bounds__(256)
void gather_kernel(const float* __restrict__ feat,
                   const float* __restrict__ view_emb,
                   const float* __restrict__ pos_w,
                   const float* __restrict__ pos_b,
                   int Ntok)
{
    int wid  = (blockIdx.x * blockDim.x + threadIdx.x) >> 5;
    int lane = threadIdx.x & 31;
    if (wid >= Ntok) return;

    int   cam = g_selcam[wid];
    float u = g_selu[wid], v = g_selv[wid], z = g_selz[wid];
    float uf = u * g_scal[2], vf = v * g_scal[3];
    float x0f = floorf(uf), y0f = floorf(vf);
    float fx = uf - x0f, fy = vf - y0f;
    int x0 = (int)x0f, y0 = (int)y0f;
    float w00 = (1.f-fx)*(1.f-fy);
    float w01 = fx*(1.f-fy);
    float w10 = (1.f-fx)*fy;
    float w11 = fx*fy;
    float zm  = (z > 1e-4f) ? 1.0f : 0.0f;

    float s0 = 0.f, s1 = 0.f;
    #pragma unroll
    for (int dy = 0; dy < 2; dy++) {
        #pragma unroll
        for (int dx = 0; dx < 2; dx++) {
            int xi = x0 + dx, yi = y0 + dy;
            bool val = (xi >= 0) && (xi < WP) && (yi >= 0) && (yi < HP);
            int xc = min(max(xi, 0), WP-1);
            int yc = min(max(yi, 0), HP-1);
            size_t base = (((size_t)cam*HP + yc)*WP + xc) * C_;
            float w = dy ? (dx ? w11 : w10) : (dx ? w01 : w00);
            float f0 = feat[base + lane];
            float f1 = feat[base + lane + 32];
            if (!val) { f0 = 0.f; f1 = 0.f; }
            s0 += w * f0;
            s1 += w * f1;
        }
    }
    size_t xb = (size_t)wid * 96;
    split_store(g_xh, g_xl, xb + lane,      s0 * zm);
    split_store(g_xh, g_xl, xb + 32 + lane, s1 * zm);

    int tdx = cam / V_;
    int vdx = cam % V_;
    int vmin = min(vdx, 63);
    float acc = pos_b[lane];
    #pragma unroll
    for (int i = 0; i < TE; i++)
        acc += g_temb[tdx*TE + i] * pos_w[i*32 + lane];
    #pragma unroll
    for (int i = 0; i < VE; i++)
        acc += view_emb[vmin*VE + i] * pos_w[(TE + i)*32 + lane];
    split_store(g_xh, g_xl, xb + 64 + lane, acc);
}

// ---------------- shared helpers ----------------
__device__ __forceinline__ void mma16816(float* c, const uint32_t* a, uint32_t b0, uint32_t b1) {
    asm volatile(
        "mma.sync.aligned.m16n8k16.row.col.f32.f16.f16.f32 "
        "{%0,%1,%2,%3}, {%4,%5,%6,%7}, {%8,%9}, {%0,%1,%2,%3};\n"
        : "+f"(c[0]), "+f"(c[1]), "+f"(c[2]), "+f"(c[3])
        : "r"(a[0]), "r"(a[1]), "r"(a[2]), "r"(a[3]), "r"(b0), "r"(b1));
}
__device__ __forceinline__ void ldsm4(uint32_t* r, uint32_t addr) {
    asm volatile("ldmatrix.sync.aligned.m8n8.x4.shared.b16 {%0,%1,%2,%3}, [%4];"
        : "=r"(r[0]), "=r"(r[1]), "=r"(r[2]), "=r"(r[3]) : "r"(addr));
}
__device__ __forceinline__ void cpa16(uint32_t dst, const void* src, int sz) {
    asm volatile("cp.async.cg.shared.global [%0], [%1], 16, %2;\n" :: "r"(dst), "l"(src), "r"(sz));
}
__device__ __forceinline__ void cp_commit() { asm volatile("cp.async.commit_group;\n"); }
__device__ __forceinline__ void cp_wait0()  { asm volatile("cp.async.wait_group 0;\n"); }

extern __shared__ __half s_dyn[];

// ---- 2-MMA compensated GEMM, BM=BN=128, BK=64, unified h/m loop, 1 sync/tile ----
// D = (31/32)*sum(Ah*Bh) + sum(Am8*Bm4). mode: 1=relu, 2=fp32 out, 4=half out.
#define SKB 72                              // halves per smem row (144 B)
#define A2_B (128*SKB*2)                    // 18432 per array
#define ST2_B (2*A2_B)                      // 36864 per stage (A+B)

__global__ __launch_bounds__(256, 2)
void gemm_tc2(const __half* __restrict__ Ah, const __half* __restrict__ Am,
              const __half* __restrict__ Bh, const __half* __restrict__ Bm,
              const float* __restrict__ bias, float* __restrict__ C,
              __half* __restrict__ Ch, __half* __restrict__ Cm,
              int N, int Kd, int Nout, int mode)
{
    int bm = blockIdx.y * 128;
    int bn = blockIdx.x * 128;
    int tid = threadIdx.x;
    int wid = tid >> 5, lane = tid & 31;
    int g = lane >> 2, tc = lane & 3;
    int wm = (wid >> 2) * 64;
    int wn = (wid & 3) * 32;
    uint32_t sb = (uint32_t)__cvta_generic_to_shared(s_dyn);

    uint32_t a_off[4];
    #pragma unroll
    for (int i = 0; i < 4; i++)
        a_off[i] = (uint32_t)(((wm + i*16 + (lane & 15)) * SKB + ((lane >> 4) << 3)) * 2);
    uint32_t b_off[2];
    #pragma unroll
    for (int jp = 0; jp < 2; jp++)
        b_off[jp] = (uint32_t)(((wn + jp*16 + (lane & 7) + ((lane >> 4) << 3)) * SKB
                                + (((lane >> 3) & 1) << 3)) * 2);

    float acc[4][4][4];
    #pragma unroll
    for (int i = 0; i < 4; i++)
        #pragma unroll
        for (int j = 0; j < 4; j++)
            #pragma unroll
            for (int r = 0; r < 4; r++) acc[i][j][r] = 0.f;

    const int NTt = (Kd + 63) >> 6;

    auto load_stage = [&](int st, int k0, const __half* Ap, const __half* Bp) {
        #pragma unroll
        for (int r = 0; r < 4; r++) {
            int id  = tid + r*256;
            int row = id >> 3, seg = id & 7;
            uint32_t d = sb + st*ST2_B + row*(SKB*2) + seg*16;
            int gr = bm + row;
            int kk = k0 + seg*8;
            bool ok = (gr < N) && (kk + 8 <= Kd);
            cpa16(d, Ap + (size_t)(ok ? gr : 0) * Kd + (ok ? kk : 0), ok ? 16 : 0);
        }
        #pragma unroll
        for (int r = 0; r < 4; r++) {
            int id  = tid + r*256;
            int row = id >> 3, seg = id & 7;
            uint32_t d = sb + st*ST2_B + A2_B + row*(SKB*2) + seg*16;
            int gn = bn + row;
            int kk = k0 + seg*8;
            bool ok = (gn < Nout) && (kk + 8 <= Kd);
            cpa16(d, Bp + (size_t)(ok ? gn : 0) * Kd + (ok ? kk : 0), ok ? 16 : 0);
        }
        cp_commit();
    };

    load_stage(0, 0, Ah, Bh);

    const int NT2 = 2 * NTt;
    for (int t = 0; t < NT2; t++) {
        cp_wait0();
        __syncthreads();
        int tn = t + 1;
        if (tn < NT2) {
            bool m2 = tn >= NTt;
            load_stage(tn & 1, (m2 ? tn - NTt : tn) * 64, m2 ? Am : Ah, m2 ? Bm : Bh);
        }
        if (t == NTt) {
            #pragma unroll
            for (int i = 0; i < 4; i++)
                #pragma unroll
                for (int j = 0; j < 4; j++)
                    #pragma unroll
                    for (int r = 0; r < 4; r++) acc[i][j][r] *= (31.0f/32.0f);
        }

        uint32_t sa  = sb + (t & 1)*ST2_B;
        uint32_t sbb = sa + A2_B;

        #pragma unroll
        for (int kb = 0; kb < 64; kb += 16) {
            uint32_t kbB = kb * 2;
            uint32_t ah[4][4];
            #pragma unroll
            for (int i = 0; i < 4; i++)
                ldsm4(ah[i], sa + a_off[i] + kbB);
            #pragma unroll
            for (int jp = 0; jp < 2; jp++) {
                uint32_t bh[4];
                ldsm4(bh, sbb + b_off[jp] + kbB);
                #pragma unroll
                for (int jj = 0; jj < 2; jj++) {
                    int j = jp*2 + jj;
                    #pragma unroll
                    for (int i = 0; i < 4; i++)
                        mma16816(acc[i][j], ah[i], bh[jj*2], bh[jj*2+1]);
                }
            }
        }
    }

    bool relu  = mode & 1;
    bool wfp   = mode & 2;
    bool whalf = mode & 4;
    #pragma unroll
    for (int j = 0; j < 4; j++) {
        int col = bn + wn + j*8 + tc*2;
        if (col >= Nout) continue;
        float bx = bias[col], by = bias[col+1];
        #pragma unroll
        for (int i = 0; i < 4; i++) {
            int r0 = bm + wm + i*16 + g;
            int r1 = r0 + 8;
            float v0 = acc[i][j][0] + bx;
            float v1 = acc[i][j][1] + by;
            float v2 = acc[i][j][2] + bx;
            float v3 = acc[i][j][3] + by;
            if (relu) {
                v0 = fmaxf(v0, 0.f); v1 = fmaxf(v1, 0.f);
                v2 = fmaxf(v2, 0.f); v3 = fmaxf(v3, 0.f);
            }
            if (r0 < N) {
                size_t o = (size_t)r0*Nout + col;
                if (wfp) { C[o] = v0; C[o+1] = v1; }
                if (whalf) {
                    __half h0 = __float2half_rn(v0), h1 = __float2half_rn(v1);
                    float f0 = __half2float(h0), f1 = __half2float(h1);
                    *(__half2*)(Ch + o) = __halves2half2(h0, h1);
                    *(__half2*)(Cm + o) = __halves2half2(
                        __float2half_rn(f0*0.125f + 4.0f*(v0 - f0)),
                        __float2half_rn(f1*0.125f + 4.0f*(v1 - f1)));
                }
            }
            if (r1 < N) {
                size_t o = (size_t)r1*Nout + col;
                if (wfp) { C[o] = v2; C[o+1] = v3; }
                if (whalf) {
                    __half h2 = __float2half_rn(v2), h3 = __float2half_rn(v3);
                    float f2 = __half2float(h2), f3 = __half2float(h3);
                    *(__half2*)(Ch + o) = __halves2half2(h2, h3);
                    *(__half2*)(Cm + o) = __halves2half2(
                        __float2half_rn(f2*0.125f + 4.0f*(v2 - f2)),
                        __float2half_rn(f3*0.125f + 4.0f*(v3 - f3)));
                }
            }
        }
    }
}

// ---------------- fused GEMM + residual + LayerNorm (Nout=256), BK=64, 1 sync/tile ----------------
#define FA2_B (64*SKB*2)                    // 9216
#define FB2_B (256*SKB*2)                   // 36864
#define FST2  (FA2_B + FB2_B)               // 46080 per stage
#define FRED2 (2*FST2)                      // 92160
#define FTOT2 (FRED2 + 64*4*8)              // 94208

__global__ __launch_bounds__(256, 2)
void gemm_ln(const __half* __restrict__ Ah, const __half* __restrict__ Am,
             const __half* __restrict__ Bh, const __half* __restrict__ Bm,
             const float* __restrict__ bias,
             const float* __restrict__ lns, const float* __restrict__ lnb,
             float* __restrict__ Hres, __half* __restrict__ Ch, __half* __restrict__ Cm,
             int N, int Kd)
{
    int bm = blockIdx.x * 64;
    int tid = threadIdx.x;
    int wid = tid >> 5, lane = tid & 31;
    int g = lane >> 2, tc = lane & 3;
    int wr = wid >> 2;
    int wc = wid & 3;
    uint32_t sb = (uint32_t)__cvta_generic_to_shared(s_dyn);
    float2* red = (float2*)((char*)s_dyn + FRED2);

    uint32_t a_off[2];
    #pragma unroll
    for (int i = 0; i < 2; i++)
        a_off[i] = (uint32_t)(((wr*32 + i*16 + (lane & 15)) * SKB + ((lane >> 4) << 3)) * 2);
    uint32_t b_off[4];
    #pragma unroll
    for (int jp = 0; jp < 4; jp++)
        b_off[jp] = (uint32_t)(((wc*64 + jp*16 + (lane & 7) + ((lane >> 4) << 3)) * SKB
                                + (((lane >> 3) & 1) << 3)) * 2);

    float acc[2][8][4];
    #pragma unroll
    for (int i = 0; i < 2; i++)
        #pragma unroll
        for (int j = 0; j < 8; j++)
            #pragma unroll
            for (int r = 0; r < 4; r++) acc[i][j][r] = 0.f;

    const int NTt = (Kd + 63) >> 6;

    auto load_stage = [&](int st, int k0, const __half* Ap, const __half* Bp) {
        #pragma unroll
        for (int r = 0; r < 2; r++) {
            int id  = tid + r*256;
            int row = id >> 3, seg = id & 7;
            uint32_t d = sb + st*FST2 + row*(SKB*2) + seg*16;
            int gr = bm + row;
            int kk = k0 + seg*8;
            bool ok = (gr < N) && (kk + 8 <= Kd);
            cpa16(d, Ap + (size_t)(ok ? gr : 0) * Kd + (ok ? kk : 0), ok ? 16 : 0);
        }
        #pragma unroll
        for (int r = 0; r < 8; r++) {
            int id  = tid + r*256;
            int row = id >> 3, seg = id & 7;
            uint32_t d = sb + st*FST2 + FA2_B + row*(SKB*2) + seg*16;
            int kk = k0 + seg*8;
            bool ok = (kk + 8 <= Kd);
            cpa16(d, Bp + (size_t)row * Kd + (ok ? kk : 0), ok ? 16 : 0);
        }
        cp_commit();
    };

    load_stage(0, 0, Ah, Bh);

    const int NT2 = 2 * NTt;
    for (int t = 0; t < NT2; t++) {
        cp_wait0();
        __syncthreads();
        int tn = t + 1;
        if (tn < NT2) {
            bool m2 = tn >= NTt;
            load_stage(tn & 1, (m2 ? tn - NTt : tn) * 64, m2 ? Am : Ah, m2 ? Bm : Bh);
        }
        if (t == NTt) {
            #pragma unroll
            for (int i = 0; i < 2; i++)
                #pragma unroll
                for (int j = 0; j < 8; j++)
                    #pragma unroll
                    for (int r = 0; r < 4; r++) acc[i][j][r] *= (31.0f/32.0f);
        }

        uint32_t sa  = sb + (t & 1)*FST2;
        uint32_t sbb = sa + FA2_B;

        #pragma unroll
        for (int kb = 0; kb < 64; kb += 16) {
            uint32_t kbB = kb * 2;
            uint32_t ah[2][4];
            #pragma unroll
            for (int i = 0; i < 2; i++)
                ldsm4(ah[i], sa + a_off[i] + kbB);
            #pragma unroll
            for (int jp = 0; jp < 4; jp++) {
                uint32_t bh[4];
                ldsm4(bh, sbb + b_off[jp] + kbB);
                #pragma unroll
                for (int jj = 0; jj < 2; jj++) {
                    int j = jp*2 + jj;
                    #pragma unroll
                    for (int i = 0; i < 2; i++)
                        mma16816(acc[i][j], ah[i], bh[jj*2], bh[jj*2+1]);
                }
            }
        }
    }
    __syncthreads();   // order tile-loop compute before red-buffer reuse below

    // ---- epilogue: x = h_old + (acc + bias); per-row LN over 256 cols ----
    int colw = wc*64;
    #pragma unroll
    for (int i = 0; i < 2; i++) {
        int rbase = wr*32 + i*16 + g;
        #pragma unroll
        for (int hhf = 0; hhf < 2; hhf++) {
            int rl = rbase + hhf*8;
            int grow = bm + rl;
            bool rv = grow < N;
            const float* hrow = Hres + (size_t)grow*256;
            float s1 = 0.f, s2 = 0.f;
            #pragma unroll
            for (int j = 0; j < 8; j++) {
                int col = colw + j*8 + tc*2;
                float2 hv = rv ? *(const float2*)(hrow + col) : make_float2(0.f, 0.f);
                float x0 = acc[i][j][hhf*2+0] + bias[col]   + hv.x;
                float x1 = acc[i][j][hhf*2+1] + bias[col+1] + hv.y;
                acc[i][j][hhf*2+0] = x0;
                acc[i][j][hhf*2+1] = x1;
                s1 += x0 + x1;
                s2 += x0*x0 + x1*x1;
            }
            s1 += __shfl_xor_sync(0xFFFFFFFFu, s1, 1);
            s1 += __shfl_xor_sync(0xFFFFFFFFu, s1, 2);
            s2 += __shfl_xor_sync(0xFFFFFFFFu, s2, 1);
            s2 += __shfl_xor_sync(0xFFFFFFFFu, s2, 2);
            if (tc == 0) red[(rl << 2) + wc] = make_float2(s1, s2);
        }
    }
    __syncthreads();
    #pragma unroll
    for (int i = 0; i < 2; i++) {
        int rbase = wr*32 + i*16 + g;
        #pragma unroll
        for (int hhf = 0; hhf < 2; hhf++) {
            int rl = rbase + hhf*8;
            int grow = bm + rl;
            if (grow >= N) continue;
            float2 t0 = red[(rl<<2)+0], t1 = red[(rl<<2)+1];
            float2 t2 = red[(rl<<2)+2], t3 = red[(rl<<2)+3];
            float tS  = t0.x + t1.x + t2.x + t3.x;
            float tS2 = t0.y + t1.y + t2.y + t3.y;
            float mu  = tS * (1.0f/256.0f);
            float var = tS2 * (1.0f/256.0f) - mu*mu;
            float rinv = rsqrtf(var + 1e-5f);
            float* hrow = Hres + (size_t)grow*256;
            size_t ob = (size_t)grow*256;
            #pragma unroll
            for (int j = 0; j < 8; j++) {
                int col = colw + j*8 + tc*2;
                float y0 = (acc[i][j][hhf*2+0] - mu)*rinv*lns[col]   + lnb[col];
                float y1 = (acc[i][j][hhf*2+1] - mu)*rinv*lns[col+1] + lnb[col+1];
                *(float2*)(hrow + col) = make_float2(y0, y1);
                __half h0 = __float2half_rn(y0), h1 = __float2half_rn(y1);
                float f0 = __half2float(h0), f1 = __half2float(h1);
                *(__half2*)(Ch + ob + col) = __halves2half2(h0, h1);
                *(__half2*)(Cm + ob + col) = __halves2half2(
                    __float2half_rn(f0*0.125f + 4.0f*(y0 - f0)),
                    __float2half_rn(f1*0.125f + 4.0f*(y1 - f1)));
            }
        }
    }
}

// ---------------- attention over 4 tokens, 8 heads, Dh=32 -> o h/m8 ----------------
__global__ __launch_bounds__(256)
void attn_kernel(int M)
{
    int m = blockIdx.x;
    if (m >= M) return;
    int h = threadIdx.x >> 5;
    int lane = threadIdx.x & 31;
    const float* qkv = g_qkv + (size_t)m * KSEL * 768;

    float q[4], k[4], v[4];
    #pragma unroll
    for (int j = 0; j < 4; j++) {
        q[j] = qkv[(size_t)j*768 +        h*32 + lane];
        k[j] = qkv[(size_t)j*768 + 256  + h*32 + lane];
        v[j] = qkv[(size_t)j*768 + 512  + h*32 + lane];
    }
    float s[16];
    #pragma unroll
    for (int i = 0; i < 4; i++)
        #pragma unroll
        for (int j = 0; j < 4; j++)
            s[i*4+j] = q[i] * k[j];
    #pragma unroll
    for (int off = 16; off > 0; off >>= 1)
        #pragma unroll
        for (int x = 0; x < 16; x++)
            s[x] += __shfl_xor_sync(0xFFFFFFFFu, s[x], off);

    const float scale = 0.17677669529663687f;
    float a[16];
    #pragma unroll
    for (int i = 0; i < 4; i++) {
        float s0 = s[i*4+0]*scale, s1 = s[i*4+1]*scale;
        float s2 = s[i*4+2]*scale, s3 = s[i*4+3]*scale;
        float mx = fmaxf(fmaxf(s0, s1), fmaxf(s2, s3));
        float e0 = expf(s0-mx), e1 = expf(s1-mx), e2 = expf(s2-mx), e3 = expf(s3-mx);
        float r = 1.0f / (e0+e1+e2+e3);
        a[i*4+0] = e0*r; a[i*4+1] = e1*r; a[i*4+2] = e2*r; a[i*4+3] = e3*r;
    }
    size_t ob = (size_t)m * KSEL * 256;
    #pragma unroll
    for (int i = 0; i < 4; i++) {
        float oi = a[i*4+0]*v[0] + a[i*4+1]*v[1] + a[i*4+2]*v[2] + a[i*4+3]*v[3];
        split_store(g_oh, g_ol, ob + (size_t)i*256 + h*32 + lane, oi);
    }
}

// ---------------- mean over the 4 tokens -> h/m8 ----------------
__global__ __launch_bounds__(256)
void mean_kernel(int M)
{
    int idx = blockIdx.x * blockDim.x + threadIdx.x;
    if (idx >= M*256) return;
    int m = idx >> 8, c = idx & 255;
    const float* hp = g_h + (size_t)m*4*256 + c;
    split_store(g_mh, g_ml, idx, 0.25f * (hp[0] + hp[256] + hp[512] + hp[768]));
}

// ---------------- host launch ----------------
extern "C" void kernel_launch(void* const* d_in, const int* in_sizes, int n_in,
                              void* d_out, int out_size)
{
    const float* xyz      = (const float*)d_in[0];
    const float* feat     = (const float*)d_in[1];
    const float* poses    = (const float*)d_in[2];
    const float* intr     = (const float*)d_in[3];
    const int*   time_ids = (const int*)  d_in[4];
    const float* view_emb = (const float*)d_in[5];
    const float* pos_w    = (const float*)d_in[6];
    const float* pos_b    = (const float*)d_in[7];
    const float* fp_w     = (const float*)d_in[8];
    const float* fp_b     = (const float*)d_in[9];
    const float* qkv_w    = (const float*)d_in[10];
    const float* qkv_b    = (const float*)d_in[11];
    const float* ao_w     = (const float*)d_in[12];
    const float* ao_b     = (const float*)d_in[13];
    const float* ln1_s    = (const float*)d_in[14];
    const float* ln1_b    = (const float*)d_in[15];
    const float* ff1_w    = (const float*)d_in[16];
    const float* ff1_b    = (const float*)d_in[17];
    const float* ff2_w    = (const float*)d_in[18];
    const float* ff2_b    = (const float*)d_in[19];
    const float* ln2_s    = (const float*)d_in[20];
    const float* ln2_b    = (const float*)d_in[21];
    const float* out_w    = (const float*)d_in[22];
    const float* out_b    = (const float*)d_in[23];

    int M    = in_sizes[0] / 3;
    int Ntok = M * KSEL;
    int T    = in_sizes[4];

    float *ph, *pqkv;
    __half *pxh,*pxl,*phh,*phl,*poh,*pol,*pfh,*pfl,*pmh,*pml,*pwh,*pwl;
    cudaGetSymbolAddress((void**)&ph,    g_h);
    cudaGetSymbolAddress((void**)&pqkv,  g_qkv);
    cudaGetSymbolAddress((void**)&pxh, g_xh); cudaGetSymbolAddress((void**)&pxl, g_xl);
    cudaGetSymbolAddress((void**)&phh, g_hh); cudaGetSymbolAddress((void**)&phl, g_hl);
    cudaGetSymbolAddress((void**)&poh, g_oh); cudaGetSymbolAddress((void**)&pol, g_ol);
    cudaGetSymbolAddress((void**)&pfh, g_fh); cudaGetSymbolAddress((void**)&pfl, g_fl);
    cudaGetSymbolAddress((void**)&pmh, g_mh); cudaGetSymbolAddress((void**)&pml, g_ml);
    cudaGetSymbolAddress((void**)&pwh, g_wh); cudaGetSymbolAddress((void**)&pwl, g_wl);

    cudaFuncSetAttribute(gemm_tc2, cudaFuncAttributeMaxDynamicSharedMemorySize, 2*ST2_B);
    cudaFuncSetAttribute(gemm_ln,  cudaFuncAttributeMaxDynamicSharedMemorySize, FTOT2);

    const long long off_fp   = 0;
    const long long off_qkv0 = off_fp   + 24576;
    const long long off_qkv1 = off_qkv0 + 196608;
    const long long off_ao0  = off_qkv1 + 196608;
    const long long off_ao1  = off_ao0  + 65536;
    const long long off_ff10 = off_ao1  + 65536;
    const long long off_ff11 = off_ff10 + 131072;
    const long long off_ff20 = off_ff11 + 131072;
    const long long off_ff21 = off_ff20 + 131072;
    const long long off_out  = off_ff21 + 131072;

    WTab tab;
    tab.src[0]=fp_w;            tab.off[0]=off_fp;   tab.kd[0]=96;  tab.nout[0]=256;
    tab.src[1]=qkv_w;           tab.off[1]=off_qkv0; tab.kd[1]=256; tab.nout[1]=768;
    tab.src[2]=qkv_w+256*768;   tab.off[2]=off_qkv1; tab.kd[2]=256; tab.nout[2]=768;
    tab.src[3]=ao_w;            tab.off[3]=off_ao0;  tab.kd[3]=256; tab.nout[3]=256;
    tab.src[4]=ao_w+256*256;    tab.off[4]=off_ao1;  tab.kd[4]=256; tab.nout[4]=256;
    tab.src[5]=ff1_w;           tab.off[5]=off_ff10; tab.kd[5]=256; tab.nout[5]=512;
    tab.src[6]=ff1_w+256*512;   tab.off[6]=off_ff11; tab.kd[6]=256; tab.nout[6]=512;
    tab.src[7]=ff2_w;           tab.off[7]=off_ff20; tab.kd[7]=512; tab.nout[7]=256;
    tab.src[8]=ff2_w+512*256;   tab.off[8]=off_ff21; tab.kd[8]=512; tab.nout[8]=256;
    tab.src[9]=out_w;           tab.off[9]=off_out;  tab.kd[9]=256; tab.nout[9]=64;
    wconv_all<<<dim3(768, 10), 256>>>(tab, pwh, pwl);

    setup_kernel<<<1, 32>>>(poses, intr, time_ids, T);
    proj_topk_kernel<<<(M + 127)/128, 128>>>(xyz, M);
    gather_kernel<<<(Ntok*32 + 255)/256, 256>>>(feat, view_emb, pos_w, pos_b, Ntok);

    auto gemm = [&](const __half* Ahp, const __half* Amp, long long woff,
                    const float* bias, float* C, __half* Ch, __half* Cm,
                    int N, int Kd, int Nout, int mode) {
        dim3 grid((Nout + 127)/128, (N + 127)/128);
        gemm_tc2<<<grid, 256, 2*ST2_B>>>(Ahp, Amp, pwh + woff, pwl + woff,
                                         bias, C, Ch, Cm, N, Kd, Nout, mode);
    };

    // fp: xin -> h (fp32 + halves)
    gemm(pxh, pxl, off_fp, fp_b, ph, phh, phl, Ntok, 96, 256, 2|4);

    const long long qoff[2]  = {off_qkv0, off_qkv1};
    const long long aoff[2]  = {off_ao0,  off_ao1};
    const long long f1off[2] = {off_ff10, off_ff11};
    const long long f2off[2] = {off_ff20, off_ff21};
    int gln = (Ntok + 63)/64;
    for (int l = 0; l < 2; l++) {
        gemm(phh, phl, qoff[l], qkv_b + l*768, pqkv, nullptr, nullptr, Ntok, 256, 768, 2);
        attn_kernel<<<M, 256>>>(M);
        gemm_ln<<<gln, 256, FTOT2>>>(poh, pol, pwh + aoff[l], pwl + aoff[l],
                                     ao_b + l*256, ln1_s + l*256, ln1_b + l*256,
                                     ph, phh, phl, Ntok, 256);
        gemm(phh, phl, f1off[l], ff1_b + l*512, nullptr, pfh, pfl, Ntok, 256, 512, 4|1);
        gemm_ln<<<gln, 256, FTOT2>>>(pfh, pfl, pwh + f2off[l], pwl + f2off[l],
                                     ff2_b + l*256, ln2_s + l*256, ln2_b + l*256,
                                     ph, phh, phl, Ntok, 512);
    }

    mean_kernel<<<(M*256 + 255)/256, 256>>>(M);
    gemm(pmh, pml, off_out, out_b, (float*)d_out, nullptr, nullptr, M, 256, 64, 2);
}

// round 17
// speedup vs baseline: 1.0251x; 1.0047x over previous
// v17: 3-stage cp.async pipeline in gemm_tc2 (gemm_ln unchanged 2-stage)
#include <cuda_runtime.h>
#include <cuda_fp16.h>
#include <math.h>
#include <stdint.h>

// ---------------- problem constants ----------------
#define T_    4
#define V_    8
#define TVC   32
#define HP    64
#define WP    64
#define C_    64
#define KSEL  4
#define HID   256
#define TE    32
#define VE    16
#define MAXM  50000
#define MAXTOK (MAXM*KSEL)

// ---------------- scratch ----------------
__device__ float g_P[TVC*12];
__device__ float g_scal[4];
__device__ float g_temb[T_*TE];
__device__ int   g_selcam[MAXTOK];
__device__ float g_selu[MAXTOK];
__device__ float g_selv[MAXTOK];
__device__ float g_selz[MAXTOK];

// fp32 intermediates
__device__ float g_h   [(size_t)MAXTOK*256];
__device__ float g_qkv [(size_t)MAXTOK*768];

// half (h, m/8) activation buffers
__device__ __half g_xh[(size_t)MAXTOK*96],  g_xl[(size_t)MAXTOK*96];
__device__ __half g_hh[(size_t)MAXTOK*256], g_hl[(size_t)MAXTOK*256];
__device__ __half g_oh[(size_t)MAXTOK*256], g_ol[(size_t)MAXTOK*256];
__device__ __half g_fh[(size_t)MAXTOK*512], g_fl[(size_t)MAXTOK*512];
__device__ __half g_mh[(size_t)MAXM*256],   g_ml[(size_t)MAXM*256];

// preconverted transposed weights [Nout][Kd], (h, m/4)
#define WTOTAL 1089536
__device__ __half g_wh[WTOTAL], g_wl[WTOTAL];

// ---------------- setup ----------------
__global__ void setup_kernel(const float* __restrict__ poses,
                             const float* __restrict__ intr,
                             const int*   __restrict__ time_ids,
                             int T)
{
    int n = threadIdx.x;
    if (n < TVC) {
        double a[4][8];
        for (int r = 0; r < 4; r++)
            for (int c = 0; c < 4; c++) {
                a[r][c]   = (double)poses[n*16 + r*4 + c];
                a[r][4+c] = (r == c) ? 1.0 : 0.0;
            }
        for (int col = 0; col < 4; col++) {
            int piv = col;
            for (int r = col+1; r < 4; r++)
                if (fabs(a[r][col]) > fabs(a[piv][col])) piv = r;
            if (piv != col)
                for (int c = 0; c < 8; c++) { double t = a[col][c]; a[col][c] = a[piv][c]; a[piv][c] = t; }
            double dv = a[col][col];
            for (int c = 0; c < 8; c++) a[col][c] /= dv;
            for (int r = 0; r < 4; r++) if (r != col) {
                double f = a[r][col];
                for (int c = 0; c < 8; c++) a[r][c] -= f * a[col][c];
            }
        }
        double Km[9];
        for (int i = 0; i < 9; i++) Km[i] = (double)intr[n*9 + i];
        for (int r = 0; r < 3; r++)
            for (int c = 0; c < 4; c++) {
                double s = 0.0;
                for (int j = 0; j < 3; j++) s += Km[r*3 + j] * a[j][4 + c];
                g_P[n*12 + r*4 + c] = (float)s;
            }
    }
    if (n == 0) {
        float cx = intr[2], cy = intr[5];
        float W = 2.0f*cx, H = 2.0f*cy;
        g_scal[0] = W; g_scal[1] = H;
        g_scal[2] = (float)WP / fmaxf(1.0f, W);
        g_scal[3] = (float)HP / fmaxf(1.0f, H);
        int tmin = time_ids[0], tmax = time_ids[0];
        for (int t = 1; t < T; t++) {
            int v = time_ids[t];
            if (v < tmin) tmin = v;
            if (v > tmax) tmax = v;
        }
        if (tmax < tmin + 1) tmax = tmin + 1;
        for (int t = 0; t < T; t++) {
            double tn = (double)(time_ids[t] - tmin) / (double)(tmax - tmin);
            for (int i = 0; i < TE/2; i++) {
                double f  = exp(8.0 * (double)i / (double)(TE/2 - 1));
                double ph = tn * f;
                g_temb[t*TE + i]        = (float)sin(ph);
                g_temb[t*TE + TE/2 + i] = (float)cos(ph);
            }
        }
    }
}

// ---------------- single-launch weight convert + transpose ----------------
struct WTab {
    const float* src[10];
    long long    off[10];
    int          kd[10];
    int          nout[10];
};
__global__ __launch_bounds__(256)
void wconv_all(WTab tab, __half* __restrict__ Wh, __half* __restrict__ Wl)
{
    int mi  = blockIdx.y;
    int idx = blockIdx.x * blockDim.x + threadIdx.x;
    int Kd = tab.kd[mi], Nout = tab.nout[mi];
    if (idx >= Kd * Nout) return;
    int n = idx / Kd, k = idx - n*Kd;
    float w = tab.src[mi][(size_t)k*Nout + n];
    __half h = __float2half_rn(w);
    float hf = __half2float(h);
    float l  = w - hf;
    size_t o = (size_t)tab.off[mi] + idx;
    Wh[o] = h;
    Wl[o] = __float2half_rn(hf*0.25f + 8.0f*l);
}

// ---------------- per-point projection + stable top-4 ----------------
__global__ __launch_bounds__(128)
void proj_topk_kernel(const float* __restrict__ xyz, int M)
{
    int m = blockIdx.x * blockDim.x + threadIdx.x;
    if (m >= M) return;
    float X = xyz[3*m+0], Y = xyz[3*m+1], Z = xyz[3*m+2];
    float W = g_scal[0], H = g_scal[1];

    float bs[KSEL] = {-1.f,-1.f,-1.f,-1.f};
    int   bi[KSEL] = {1000,1000,1000,1000};
    float bu[KSEL], bv[KSEL], bz[KSEL];
    #pragma unroll
    for (int q = 0; q < KSEL; q++) { bu[q]=0; bv[q]=0; bz[q]=0; }

    for (int cam = 0; cam < TVC; cam++) {
        const float* P = g_P + cam*12;
        float uw = P[0]*X + P[1]*Y + P[2] *Z + P[3];
        float vw = P[4]*X + P[5]*Y + P[6] *Z + P[7];
        float z  = P[8]*X + P[9]*Y + P[10]*Z + P[11];
        float wd = fmaxf(z, 1e-6f);
        float u = uw / wd, v = vw / wd;
        bool vis = (z > 1e-4f) && (u >= 0.f) && (u < W) && (v >= 0.f) && (v < H);
        float score = vis ? (1.0f / (fmaxf(z, 0.1f) + 1e-6f)) : 0.0f;
        #pragma unroll
        for (int slot = 0; slot < KSEL; slot++) {
            bool better = (score > bs[slot]) || (score == bs[slot] && cam < bi[slot]);
            if (better) {
                for (int q = KSEL-1; q > slot; q--) {
                    bs[q]=bs[q-1]; bi[q]=bi[q-1]; bu[q]=bu[q-1]; bv[q]=bv[q-1]; bz[q]=bz[q-1];
                }
                bs[slot]=score; bi[slot]=cam; bu[slot]=u; bv[slot]=v; bz[slot]=z;
                break;
            }
        }
    }
    #pragma unroll
    for (int q = 0; q < KSEL; q++) {
        int t = m*KSEL + q;
        g_selcam[t] = bi[q];
        g_selu[t] = bu[q]; g_selv[t] = bv[q]; g_selz[t] = bz[q];
    }
}

// Activation split: h = RN(v), m8 = RN(h/8 + 4*(v-h))
__device__ __forceinline__ void split_store(__half* hp, __half* mp, size_t idx, float v) {
    __half h = __float2half_rn(v);
    float hf = __half2float(h);
    float l  = v - hf;
    hp[idx] = h;
    mp[idx] = __float2half_rn(hf*0.125f + 4.0f*l);
}

// ---------------- bilinear gather + pos feats -> xin h/m8 [Ntok,96] ----------------
__global__ __launch_bounds__(256)
void gather_kernel(const float* __restrict__ feat,
                   const float* __restrict__ view_emb,
                   const float* __restrict__ pos_w,
                   const float* __restrict__ pos_b,
                   int Ntok)
{
    int wid  = (blockIdx.x * blockDim.x + threadIdx.x) >> 5;
    int lane = threadIdx.x & 31;
    if (wid >= Ntok) return;

    int   cam = g_selcam[wid];
    float u = g_selu[wid], v = g_selv[wid], z = g_selz[wid];
    float uf = u * g_scal[2], vf = v * g_scal[3];
    float x0f = floorf(uf), y0f = floorf(vf);
    float fx = uf - x0f, fy = vf - y0f;
    int x0 = (int)x0f, y0 = (int)y0f;
    float w00 = (1.f-fx)*(1.f-fy);
    float w01 = fx*(1.f-fy);
    float w10 = (1.f-fx)*fy;
    float w11 = fx*fy;
    float zm  = (z > 1e-4f) ? 1.0f : 0.0f;

    float s0 = 0.f, s1 = 0.f;
    #pragma unroll
    for (int dy = 0; dy < 2; dy++) {
        #pragma unroll
        for (int dx = 0; dx < 2; dx++) {
            int xi = x0 + dx, yi = y0 + dy;
            bool val = (xi >= 0) && (xi < WP) && (yi >= 0) && (yi < HP);
            int xc = min(max(xi, 0), WP-1);
            int yc = min(max(yi, 0), HP-1);
            size_t base = (((size_t)cam*HP + yc)*WP + xc) * C_;
            float w = dy ? (dx ? w11 : w10) : (dx ? w01 : w00);
            float f0 = feat[base + lane];
            float f1 = feat[base + lane + 32];
            if (!val) { f0 = 0.f; f1 = 0.f; }
            s0 += w * f0;
            s1 += w * f1;
        }
    }
    size_t xb = (size_t)wid * 96;
    split_store(g_xh, g_xl, xb + lane,      s0 * zm);
    split_store(g_xh, g_xl, xb + 32 + lane, s1 * zm);

    int tdx = cam / V_;
    int vdx = cam % V_;
    int vmin = min(vdx, 63);
    float acc = pos_b[lane];
    #pragma unroll
    for (int i = 0; i < TE; i++)
        acc += g_temb[tdx*TE + i] * pos_w[i*32 + lane];
    #pragma unroll
    for (int i = 0; i < VE; i++)
        acc += view_emb[vmin*VE + i] * pos_w[(TE + i)*32 + lane];
    split_store(g_xh, g_xl, xb + 64 + lane, acc);
}

// ---------------- shared helpers ----------------
__device__ __forceinline__ void mma16816(float* c, const uint32_t* a, uint32_t b0, uint32_t b1) {
    asm volatile(
        "mma.sync.aligned.m16n8k16.row.col.f32.f16.f16.f32 "
        "{%0,%1,%2,%3}, {%4,%5,%6,%7}, {%8,%9}, {%0,%1,%2,%3};\n"
        : "+f"(c[0]), "+f"(c[1]), "+f"(c[2]), "+f"(c[3])
        : "r"(a[0]), "r"(a[1]), "r"(a[2]), "r"(a[3]), "r"(b0), "r"(b1));
}
__device__ __forceinline__ void ldsm4(uint32_t* r, uint32_t addr) {
    asm volatile("ldmatrix.sync.aligned.m8n8.x4.shared.b16 {%0,%1,%2,%3}, [%4];"
        : "=r"(r[0]), "=r"(r[1]), "=r"(r[2]), "=r"(r[3]) : "r"(addr));
}
__device__ __forceinline__ void cpa16(uint32_t dst, const void* src, int sz) {
    asm volatile("cp.async.cg.shared.global [%0], [%1], 16, %2;\n" :: "r"(dst), "l"(src), "r"(sz));
}
__device__ __forceinline__ void cp_commit() { asm volatile("cp.async.commit_group;\n"); }
__device__ __forceinline__ void cp_wait0()  { asm volatile("cp.async.wait_group 0;\n"); }
__device__ __forceinline__ void cp_wait1()  { asm volatile("cp.async.wait_group 1;\n"); }

extern __shared__ __half s_dyn[];

// ---- 2-MMA compensated GEMM, BM=BN=128, BK=64, unified h/m loop, 3-stage pipeline ----
// D = (31/32)*sum(Ah*Bh) + sum(Am8*Bm4). mode: 1=relu, 2=fp32 out, 4=half out.
#define SKB 72                              // halves per smem row (144 B)
#define A2_B (128*SKB*2)                    // 18432 per array
#define ST2_B (2*A2_B)                      // 36864 per stage (A+B)
#define NSTG 3

__global__ __launch_bounds__(256, 2)
void gemm_tc2(const __half* __restrict__ Ah, const __half* __restrict__ Am,
              const __half* __restrict__ Bh, const __half* __restrict__ Bm,
              const float* __restrict__ bias, float* __restrict__ C,
              __half* __restrict__ Ch, __half* __restrict__ Cm,
              int N, int Kd, int Nout, int mode)
{
    int bm = blockIdx.y * 128;
    int bn = blockIdx.x * 128;
    int tid = threadIdx.x;
    int wid = tid >> 5, lane = tid & 31;
    int g = lane >> 2, tc = lane & 3;
    int wm = (wid >> 2) * 64;
    int wn = (wid & 3) * 32;
    uint32_t sb = (uint32_t)__cvta_generic_to_shared(s_dyn);

    uint32_t a_off[4];
    #pragma unroll
    for (int i = 0; i < 4; i++)
        a_off[i] = (uint32_t)(((wm + i*16 + (lane & 15)) * SKB + ((lane >> 4) << 3)) * 2);
    uint32_t b_off[2];
    #pragma unroll
    for (int jp = 0; jp < 2; jp++)
        b_off[jp] = (uint32_t)(((wn + jp*16 + (lane & 7) + ((lane >> 4) << 3)) * SKB
                                + (((lane >> 3) & 1) << 3)) * 2);

    float acc[4][4][4];
    #pragma unroll
    for (int i = 0; i < 4; i++)
        #pragma unroll
        for (int j = 0; j < 4; j++)
            #pragma unroll
            for (int r = 0; r < 4; r++) acc[i][j][r] = 0.f;

    const int NTt = (Kd + 63) >> 6;
    const int NT2 = 2 * NTt;

    auto load_tile = [&](int t, int st) {
        bool m2 = t >= NTt;
        int k0 = (m2 ? t - NTt : t) * 64;
        const __half* Ap = m2 ? Am : Ah;
        const __half* Bp = m2 ? Bm : Bh;
        #pragma unroll
        for (int r = 0; r < 4; r++) {
            int id  = tid + r*256;
            int row = id >> 3, seg = id & 7;
            uint32_t d = sb + st*ST2_B + row*(SKB*2) + seg*16;
            int gr = bm + row;
            int kk = k0 + seg*8;
            bool ok = (gr < N) && (kk + 8 <= Kd);
            cpa16(d, Ap + (size_t)(ok ? gr : 0) * Kd + (ok ? kk : 0), ok ? 16 : 0);
        }
        #pragma unroll
        for (int r = 0; r < 4; r++) {
            int id  = tid + r*256;
            int row = id >> 3, seg = id & 7;
            uint32_t d = sb + st*ST2_B + A2_B + row*(SKB*2) + seg*16;
            int gn = bn + row;
            int kk = k0 + seg*8;
            bool ok = (gn < Nout) && (kk + 8 <= Kd);
            cpa16(d, Bp + (size_t)(ok ? gn : 0) * Kd + (ok ? kk : 0), ok ? 16 : 0);
        }
        cp_commit();
    };

    // prologue: two tiles in flight (NT2 >= 2 always: Kd >= 64)
    load_tile(0, 0);
    if (NT2 > 1) load_tile(1, 1);

    for (int t = 0; t < NT2; t++) {
        if (t + 1 < NT2) cp_wait1();   // oldest (load t) complete; load(t+1) may run on
        else             cp_wait0();
        __syncthreads();
        int tn = t + 2;
        if (tn < NT2) load_tile(tn, tn % NSTG);
        if (t == NTt) {
            #pragma unroll
            for (int i = 0; i < 4; i++)
                #pragma unroll
                for (int j = 0; j < 4; j++)
                    #pragma unroll
                    for (int r = 0; r < 4; r++) acc[i][j][r] *= (31.0f/32.0f);
        }

        uint32_t sa  = sb + (t % NSTG)*ST2_B;
        uint32_t sbb = sa + A2_B;

        #pragma unroll
        for (int kb = 0; kb < 64; kb += 16) {
            uint32_t kbB = kb * 2;
            uint32_t ah[4][4];
            #pragma unroll
            for (int i = 0; i < 4; i++)
                ldsm4(ah[i], sa + a_off[i] + kbB);
            #pragma unroll
            for (int jp = 0; jp < 2; jp++) {
                uint32_t bh[4];
                ldsm4(bh, sbb + b_off[jp] + kbB);
                #pragma unroll
                for (int jj = 0; jj < 2; jj++) {
                    int j = jp*2 + jj;
                    #pragma unroll
                    for (int i = 0; i < 4; i++)
                        mma16816(acc[i][j], ah[i], bh[jj*2], bh[jj*2+1]);
                }
            }
        }
    }

    bool relu  = mode & 1;
    bool wfp   = mode & 2;
    bool whalf = mode & 4;
    #pragma unroll
    for (int j = 0; j < 4; j++) {
        int col = bn + wn + j*8 + tc*2;
        if (col >= Nout) continue;
        float bx = bias[col], by = bias[col+1];
        #pragma unroll
        for (int i = 0; i < 4; i++) {
            int r0 = bm + wm + i*16 + g;
            int r1 = r0 + 8;
            float v0 = acc[i][j][0] + bx;
            float v1 = acc[i][j][1] + by;
            float v2 = acc[i][j][2] + bx;
            float v3 = acc[i][j][3] + by;
            if (relu) {
                v0 = fmaxf(v0, 0.f); v1 = fmaxf(v1, 0.f);
                v2 = fmaxf(v2, 0.f); v3 = fmaxf(v3, 0.f);
            }
            if (r0 < N) {
                size_t o = (size_t)r0*Nout + col;
                if (wfp) { C[o] = v0; C[o+1] = v1; }
                if (whalf) {
                    __half h0 = __float2half_rn(v0), h1 = __float2half_rn(v1);
                    float f0 = __half2float(h0), f1 = __half2float(h1);
                    *(__half2*)(Ch + o) = __halves2half2(h0, h1);
                    *(__half2*)(Cm + o) = __halves2half2(
                        __float2half_rn(f0*0.125f + 4.0f*(v0 - f0)),
                        __float2half_rn(f1*0.125f + 4.0f*(v1 - f1)));
                }
            }
            if (r1 < N) {
                size_t o = (size_t)r1*Nout + col;
                if (wfp) { C[o] = v2; C[o+1] = v3; }
                if (whalf) {
                    __half h2 = __float2half_rn(v2), h3 = __float2half_rn(v3);
                    float f2 = __half2float(h2), f3 = __half2float(h3);
                    *(__half2*)(Ch + o) = __halves2half2(h2, h3);
                    *(__half2*)(Cm + o) = __halves2half2(
                        __float2half_rn(f2*0.125f + 4.0f*(v2 - f2)),
                        __float2half_rn(f3*0.125f + 4.0f*(v3 - f3)));
                }
            }
        }
    }
}

// ---------------- fused GEMM + residual + LayerNorm (Nout=256), BK=64, 2-stage ----------------
#define FA2_B (64*SKB*2)                    // 9216
#define FB2_B (256*SKB*2)                   // 36864
#define FST2  (FA2_B + FB2_B)               // 46080 per stage
#define FRED2 (2*FST2)                      // 92160
#define FTOT2 (FRED2 + 64*4*8)              // 94208

__global__ __launch_bounds__(256, 2)
void gemm_ln(const __half* __restrict__ Ah, const __half* __restrict__ Am,
             const __half* __restrict__ Bh, const __half* __restrict__ Bm,
             const float* __restrict__ bias,
             const float* __restrict__ lns, const float* __restrict__ lnb,
             float* __restrict__ Hres, __half* __restrict__ Ch, __half* __restrict__ Cm,
             int N, int Kd)
{
    int bm = blockIdx.x * 64;
    int tid = threadIdx.x;
    int wid = tid >> 5, lane = tid & 31;
    int g = lane >> 2, tc = lane & 3;
    int wr = wid >> 2;
    int wc = wid & 3;
    uint32_t sb = (uint32_t)__cvta_generic_to_shared(s_dyn);
    float2* red = (float2*)((char*)s_dyn + FRED2);

    uint32_t a_off[2];
    #pragma unroll
    for (int i = 0; i < 2; i++)
        a_off[i] = (uint32_t)(((wr*32 + i*16 + (lane & 15)) * SKB + ((lane >> 4) << 3)) * 2);
    uint32_t b_off[4];
    #pragma unroll
    for (int jp = 0; jp < 4; jp++)
        b_off[jp] = (uint32_t)(((wc*64 + jp*16 + (lane & 7) + ((lane >> 4) << 3)) * SKB
                                + (((lane >> 3) & 1) << 3)) * 2);

    float acc[2][8][4];
    #pragma unroll
    for (int i = 0; i < 2; i++)
        #pragma unroll
        for (int j = 0; j < 8; j++)
            #pragma unroll
            for (int r = 0; r < 4; r++) acc[i][j][r] = 0.f;

    const int NTt = (Kd + 63) >> 6;

    auto load_stage = [&](int st, int k0, const __half* Ap, const __half* Bp) {
        #pragma unroll
        for (int r = 0; r < 2; r++) {
            int id  = tid + r*256;
            int row = id >> 3, seg = id & 7;
            uint32_t d = sb + st*FST2 + row*(SKB*2) + seg*16;
            int gr = bm + row;
            int kk = k0 + seg*8;
            bool ok = (gr < N) && (kk + 8 <= Kd);
            cpa16(d, Ap + (size_t)(ok ? gr : 0) * Kd + (ok ? kk : 0), ok ? 16 : 0);
        }
        #pragma unroll
        for (int r = 0; r < 8; r++) {
            int id  = tid + r*256;
            int row = id >> 3, seg = id & 7;
            uint32_t d = sb + st*FST2 + FA2_B + row*(SKB*2) + seg*16;
            int kk = k0 + seg*8;
            bool ok = (kk + 8 <= Kd);
            cpa16(d, Bp + (size_t)row * Kd + (ok ? kk : 0), ok ? 16 : 0);
        }
        cp_commit();
    };

    load_stage(0, 0, Ah, Bh);

    const int NT2 = 2 * NTt;
    for (int t = 0; t < NT2; t++) {
        cp_wait0();
        __syncthreads();
        int tn = t + 1;
        if (tn < NT2) {
            bool m2 = tn >= NTt;
            load_stage(tn & 1, (m2 ? tn - NTt : tn) * 64, m2 ? Am : Ah, m2 ? Bm : Bh);
        }
        if (t == NTt) {
            #pragma unroll
            for (int i = 0; i < 2; i++)
                #pragma unroll
                for (int j = 0; j < 8; j++)
                    #pragma unroll
                    for (int r = 0; r < 4; r++) acc[i][j][r] *= (31.0f/32.0f);
        }

        uint32_t sa  = sb + (t & 1)*FST2;
        uint32_t sbb = sa + FA2_B;

        #pragma unroll
        for (int kb = 0; kb < 64; kb += 16) {
            uint32_t kbB = kb * 2;
            uint32_t ah[2][4];
            #pragma unroll
            for (int i = 0; i < 2; i++)
                ldsm4(ah[i], sa + a_off[i] + kbB);
            #pragma unroll
            for (int jp = 0; jp < 4; jp++) {
                uint32_t bh[4];
                ldsm4(bh, sbb + b_off[jp] + kbB);
                #pragma unroll
                for (int jj = 0; jj < 2; jj++) {
                    int j = jp*2 + jj;
                    #pragma unroll
                    for (int i = 0; i < 2; i++)
                        mma16816(acc[i][j], ah[i], bh[jj*2], bh[jj*2+1]);
                }
            }
        }
    }
    __syncthreads();   // order tile-loop compute before red-buffer reuse below

    // ---- epilogue: x = h_old + (acc + bias); per-row LN over 256 cols ----
    int colw = wc*64;
    #pragma unroll
    for (int i = 0; i < 2; i++) {
        int rbase = wr*32 + i*16 + g;
        #pragma unroll
        for (int hhf = 0; hhf < 2; hhf++) {
            int rl = rbase + hhf*8;
            int grow = bm + rl;
            bool rv = grow < N;
            const float* hrow = Hres + (size_t)grow*256;
            float s1 = 0.f, s2 = 0.f;
            #pragma unroll
            for (int j = 0; j < 8; j++) {
                int col = colw + j*8 + tc*2;
                float2 hv = rv ? *(const float2*)(hrow + col) : make_float2(0.f, 0.f);
                float x0 = acc[i][j][hhf*2+0] + bias[col]   + hv.x;
                float x1 = acc[i][j][hhf*2+1] + bias[col+1] + hv.y;
                acc[i][j][hhf*2+0] = x0;
                acc[i][j][hhf*2+1] = x1;
                s1 += x0 + x1;
                s2 += x0*x0 + x1*x1;
            }
            s1 += __shfl_xor_sync(0xFFFFFFFFu, s1, 1);
            s1 += __shfl_xor_sync(0xFFFFFFFFu, s1, 2);
            s2 += __shfl_xor_sync(0xFFFFFFFFu, s2, 1);
            s2 += __shfl_xor_sync(0xFFFFFFFFu, s2, 2);
            if (tc == 0) red[(rl << 2) + wc] = make_float2(s1, s2);
        }
    }
    __syncthreads();
    #pragma unroll
    for (int i = 0; i < 2; i++) {
        int rbase = wr*32 + i*16 + g;
        #pragma unroll
        for (int hhf = 0; hhf < 2; hhf++) {
            int rl = rbase + hhf*8;
            int grow = bm + rl;
            if (grow >= N) continue;
            float2 t0 = red[(rl<<2)+0], t1 = red[(rl<<2)+1];
            float2 t2 = red[(rl<<2)+2], t3 = red[(rl<<2)+3];
            float tS  = t0.x + t1.x + t2.x + t3.x;
            float tS2 = t0.y + t1.y + t2.y + t3.y;
            float mu  = tS * (1.0f/256.0f);
            float var = tS2 * (1.0f/256.0f) - mu*mu;
            float rinv = rsqrtf(var + 1e-5f);
            float* hrow = Hres + (size_t)grow*256;
            size_t ob = (size_t)grow*256;
            #pragma unroll
            for (int j = 0; j < 8; j++) {
                int col = colw + j*8 + tc*2;
                float y0 = (acc[i][j][hhf*2+0] - mu)*rinv*lns[col]   + lnb[col];
                float y1 = (acc[i][j][hhf*2+1] - mu)*rinv*lns[col+1] + lnb[col+1];
                *(float2*)(hrow + col) = make_float2(y0, y1);
                __half h0 = __float2half_rn(y0), h1 = __float2half_rn(y1);
                float f0 = __half2float(h0), f1 = __half2float(h1);
                *(__half2*)(Ch + ob + col) = __halves2half2(h0, h1);
                *(__half2*)(Cm + ob + col) = __halves2half2(
                    __float2half_rn(f0*0.125f + 4.0f*(y0 - f0)),
                    __float2half_rn(f1*0.125f + 4.0f*(y1 - f1)));
            }
        }
    }
}

// ---------------- attention over 4 tokens, 8 heads, Dh=32 -> o h/m8 ----------------
__global__ __launch_bounds__(256)
void attn_kernel(int M)
{
    int m = blockIdx.x;
    if (m >= M) return;
    int h = threadIdx.x >> 5;
    int lane = threadIdx.x & 31;
    const float* qkv = g_qkv + (size_t)m * KSEL * 768;

    float q[4], k[4], v[4];
    #pragma unroll
    for (int j = 0; j < 4; j++) {
        q[j] = qkv[(size_t)j*768 +        h*32 + lane];
        k[j] = qkv[(size_t)j*768 + 256  + h*32 + lane];
        v[j] = qkv[(size_t)j*768 + 512  + h*32 + lane];
    }
    float s[16];
    #pragma unroll
    for (int i = 0; i < 4; i++)
        #pragma unroll
        for (int j = 0; j < 4; j++)
            s[i*4+j] = q[i] * k[j];
    #pragma unroll
    for (int off = 16; off > 0; off >>= 1)
        #pragma unroll
        for (int x = 0; x < 16; x++)
            s[x] += __shfl_xor_sync(0xFFFFFFFFu, s[x], off);

    const float scale = 0.17677669529663687f;
    float a[16];
    #pragma unroll
    for (int i = 0; i < 4; i++) {
        float s0 = s[i*4+0]*scale, s1 = s[i*4+1]*scale;
        float s2 = s[i*4+2]*scale, s3 = s[i*4+3]*scale;
        float mx = fmaxf(fmaxf(s0, s1), fmaxf(s2, s3));
        float e0 = expf(s0-mx), e1 = expf(s1-mx), e2 = expf(s2-mx), e3 = expf(s3-mx);
        float r = 1.0f / (e0+e1+e2+e3);
        a[i*4+0] = e0*r; a[i*4+1] = e1*r; a[i*4+2] = e2*r; a[i*4+3] = e3*r;
    }
    size_t ob = (size_t)m * KSEL * 256;
    #pragma unroll
    for (int i = 0; i < 4; i++) {
        float oi = a[i*4+0]*v[0] + a[i*4+1]*v[1] + a[i*4+2]*v[2] + a[i*4+3]*v[3];
        split_store(g_oh, g_ol, ob + (size_t)i*256 + h*32 + lane, oi);
    }
}

// ---------------- mean over the 4 tokens -> h/m8 ----------------
__global__ __launch_bounds__(256)
void mean_kernel(int M)
{
    int idx = blockIdx.x * blockDim.x + threadIdx.x;
    if (idx >= M*256) return;
    int m = idx >> 8, c = idx & 255;
    const float* hp = g_h + (size_t)m*4*256 + c;
    split_store(g_mh, g_ml, idx, 0.25f * (hp[0] + hp[256] + hp[512] + hp[768]));
}

// ---------------- host launch ----------------
extern "C" void kernel_launch(void* const* d_in, const int* in_sizes, int n_in,
                              void* d_out, int out_size)
{
    const float* xyz      = (const float*)d_in[0];
    const float* feat     = (const float*)d_in[1];
    const float* poses    = (const float*)d_in[2];
    const float* intr     = (const float*)d_in[3];
    const int*   time_ids = (const int*)  d_in[4];
    const float* view_emb = (const float*)d_in[5];
    const float* pos_w    = (const float*)d_in[6];
    const float* pos_b    = (const float*)d_in[7];
    const float* fp_w     = (const float*)d_in[8];
    const float* fp_b     = (const float*)d_in[9];
    const float* qkv_w    = (const float*)d_in[10];
    const float* qkv_b    = (const float*)d_in[11];
    const float* ao_w     = (const float*)d_in[12];
    const float* ao_b     = (const float*)d_in[13];
    const float* ln1_s    = (const float*)d_in[14];
    const float* ln1_b    = (const float*)d_in[15];
    const float* ff1_w    = (const float*)d_in[16];
    const float* ff1_b    = (const float*)d_in[17];
    const float* ff2_w    = (const float*)d_in[18];
    const float* ff2_b    = (const float*)d_in[19];
    const float* ln2_s    = (const float*)d_in[20];
    const float* ln2_b    = (const float*)d_in[21];
    const float* out_w    = (const float*)d_in[22];
    const float* out_b    = (const float*)d_in[23];

    int M    = in_sizes[0] / 3;
    int Ntok = M * KSEL;
    int T    = in_sizes[4];

    float *ph, *pqkv;
    __half *pxh,*pxl,*phh,*phl,*poh,*pol,*pfh,*pfl,*pmh,*pml,*pwh,*pwl;
    cudaGetSymbolAddress((void**)&ph,    g_h);
    cudaGetSymbolAddress((void**)&pqkv,  g_qkv);
    cudaGetSymbolAddress((void**)&pxh, g_xh); cudaGetSymbolAddress((void**)&pxl, g_xl);
    cudaGetSymbolAddress((void**)&phh, g_hh); cudaGetSymbolAddress((void**)&phl, g_hl);
    cudaGetSymbolAddress((void**)&poh, g_oh); cudaGetSymbolAddress((void**)&pol, g_ol);
    cudaGetSymbolAddress((void**)&pfh, g_fh); cudaGetSymbolAddress((void**)&pfl, g_fl);
    cudaGetSymbolAddress((void**)&pmh, g_mh); cudaGetSymbolAddress((void**)&pml, g_ml);
    cudaGetSymbolAddress((void**)&pwh, g_wh); cudaGetSymbolAddress((void**)&pwl, g_wl);

    cudaFuncSetAttribute(gemm_tc2, cudaFuncAttributeMaxDynamicSharedMemorySize, NSTG*ST2_B);
    cudaFuncSetAttribute(gemm_ln,  cudaFuncAttributeMaxDynamicSharedMemorySize, FTOT2);

    const long long off_fp   = 0;
    const long long off_qkv0 = off_fp   + 24576;
    const long long off_qkv1 = off_qkv0 + 196608;
    const long long off_ao0  = off_qkv1 + 196608;
    const long long off_ao1  = off_ao0  + 65536;
    const long long off_ff10 = off_ao1  + 65536;
    const long long off_ff11 = off_ff10 + 131072;
    const long long off_ff20 = off_ff11 + 131072;
    const long long off_ff21 = off_ff20 + 131072;
    const long long off_out  = off_ff21 + 131072;

    WTab tab;
    tab.src[0]=fp_w;            tab.off[0]=off_fp;   tab.kd[0]=96;  tab.nout[0]=256;
    tab.src[1]=qkv_w;           tab.off[1]=off_qkv0; tab.kd[1]=256; tab.nout[1]=768;
    tab.src[2]=qkv_w+256*768;   tab.off[2]=off_qkv1; tab.kd[2]=256; tab.nout[2]=768;
    tab.src[3]=ao_w;            tab.off[3]=off_ao0;  tab.kd[3]=256; tab.nout[3]=256;
    tab.src[4]=ao_w+256*256;    tab.off[4]=off_ao1;  tab.kd[4]=256; tab.nout[4]=256;
    tab.src[5]=ff1_w;           tab.off[5]=off_ff10; tab.kd[5]=256; tab.nout[5]=512;
    tab.src[6]=ff1_w+256*512;   tab.off[6]=off_ff11; tab.kd[6]=256; tab.nout[6]=512;
    tab.src[7]=ff2_w;           tab.off[7]=off_ff20; tab.kd[7]=512; tab.nout[7]=256;
    tab.src[8]=ff2_w+512*256;   tab.off[8]=off_ff21; tab.kd[8]=512; tab.nout[8]=256;
    tab.src[9]=out_w;           tab.off[9]=off_out;  tab.kd[9]=256; tab.nout[9]=64;
    wconv_all<<<dim3(768, 10), 256>>>(tab, pwh, pwl);

    setup_kernel<<<1, 32>>>(poses, intr, time_ids, T);
    proj_topk_kernel<<<(M + 127)/128, 128>>>(xyz, M);
    gather_kernel<<<(Ntok*32 + 255)/256, 256>>>(feat, view_emb, pos_w, pos_b, Ntok);

    auto gemm = [&](const __half* Ahp, const __half* Amp, long long woff,
                    const float* bias, float* C, __half* Ch, __half* Cm,
                    int N, int Kd, int Nout, int mode) {
        dim3 grid((Nout + 127)/128, (N + 127)/128);
        gemm_tc2<<<grid, 256, NSTG*ST2_B>>>(Ahp, Amp, pwh + woff, pwl + woff,
                                            bias, C, Ch, Cm, N, Kd, Nout, mode);
    };

    // fp: xin -> h (fp32 + halves)
    gemm(pxh, pxl, off_fp, fp_b, ph, phh, phl, Ntok, 96, 256, 2|4);

    const long long qoff[2]  = {off_qkv0, off_qkv1};
    const long long aoff[2]  = {off_ao0,  off_ao1};
    const long long f1off[2] = {off_ff10, off_ff11};
    const long long f2off[2] = {off_ff20, off_ff21};
    int gln = (Ntok + 63)/64;
    for (int l = 0; l < 2; l++) {
        gemm(phh, phl, qoff[l], qkv_b + l*768, pqkv, nullptr, nullptr, Ntok, 256, 768, 2);
        attn_kernel<<<M, 256>>>(M);
        gemm_ln<<<gln, 256, FTOT2>>>(poh, pol, pwh + aoff[l], pwl + aoff[l],
                                     ao_b + l*256, ln1_s + l*256, ln1_b + l*256,
                                     ph, phh, phl, Ntok, 256);
        gemm(phh, phl, f1off[l], ff1_b + l*512, nullptr, pfh, pfl, Ntok, 256, 512, 4|1);
        gemm_ln<<<gln, 256, FTOT2>>>(pfh, pfl, pwh + f2off[l], pwl + f2off[l],
                                     ff2_b + l*256, ln2_s + l*256, ln2_b + l*256,
                                     ph, phh, phl, Ntok, 512);
    }

    mean_kernel<<<(M*256 + 255)/256, 256>>>(M);
    gemm(pmh, pml, off_out, out_b, (float*)d_out, nullptr, nullptr, M, 256, 64, 2);
}